// round 2
// baseline (speedup 1.0000x reference)
#include <cuda_runtime.h>

// ---------------------------------------------------------------------------
// MatchLSTM: B=64, premise steps TP=65, hyp steps THY=64, EMB=768, HID=512
// fp32 FFMA baseline, multi-kernel CUDA-graph pipeline.
// ---------------------------------------------------------------------------
#define BB    64
#define TP    65
#define THY   64
#define HIDN  512
#define G4    2048
#define EMBD  768
#define LL    130

// ------------------------- device scratch (no allocs) ----------------------
__device__ float g_xp[TP * BB * G4];
__device__ float g_xh[THY * BB * G4];
__device__ float g_hs[TP * BB * HIDN];
__device__ float g_ht[THY * BB * HIDN];
__device__ float g_cp[BB * HIDN];
__device__ float g_ch[BB * HIDN];
__device__ float g_wshs[TP * BB * HIDN];
__device__ float g_wtht[THY * BB * HIDN];
__device__ float g_u[BB * HIDN];
__device__ float g_mk[BB * 2 * HIDN];
__device__ float g_gm[BB * G4];
__device__ float g_hma[BB * HIDN];
__device__ float g_hmb[BB * HIDN];
__device__ float g_cm[BB * HIDN];
__device__ float g_zero[BB * HIDN];   // never written -> stays zero

// ------------------------- FFMA-only tanh / sigmoid ------------------------
__device__ __forceinline__ float tanh_fast(float x) {
    const float a1 = 4.89352455891786e-03f, a3 = 6.37261928875436e-04f,
                a5 = 1.48572235717979e-05f, a7 = 5.12229709037114e-08f,
                a9 = -8.60467152213735e-11f, a11 = 2.00018790482477e-13f,
                a13 = -2.76076847742355e-16f;
    const float b0 = 4.89352518554385e-03f, b2 = 2.26843463243900e-03f,
                b4 = 1.18534705686654e-04f, b6 = 1.19825839466702e-06f;
    x = fminf(7.90531110763549805f, fmaxf(-7.90531110763549805f, x));
    float s = x * x;
    float p = fmaf(a13, s, a11);
    p = fmaf(p, s, a9);  p = fmaf(p, s, a7);
    p = fmaf(p, s, a5);  p = fmaf(p, s, a3);
    p = fmaf(p, s, a1);  p = x * p;
    float q = fmaf(b6, s, b4);
    q = fmaf(q, s, b2);  q = fmaf(q, s, b0);
    return __fdividef(p, q);
}
__device__ __forceinline__ float sig_fast(float x) {
    return fmaf(0.5f, tanh_fast(0.5f * x), 0.5f);
}

// ------------------------- 64x64 fp32 tile loader (256 thr) ----------------
__device__ __forceinline__ void load_tile64(float sh[64][65],
                                            const float* __restrict__ src,
                                            int rowstride, int k0, int tid) {
    int bl  = tid >> 2;
    int kk0 = (tid & 3) * 16;
    const float4* s4 = (const float4*)(src + (size_t)bl * rowstride + k0 + kk0);
    float4 v0 = s4[0], v1 = s4[1], v2 = s4[2], v3 = s4[3];
    float* dst = &sh[bl][kk0];
    dst[0]=v0.x;  dst[1]=v0.y;  dst[2]=v0.z;  dst[3]=v0.w;
    dst[4]=v1.x;  dst[5]=v1.y;  dst[6]=v1.z;  dst[7]=v1.w;
    dst[8]=v2.x;  dst[9]=v2.y;  dst[10]=v2.z; dst[11]=v2.w;
    dst[12]=v3.x; dst[13]=v3.y; dst[14]=v3.z; dst[15]=v3.w;
}

// ------------------------- init recurrent state ----------------------------
__global__ void kinit() {
    int i = blockIdx.x * blockDim.x + threadIdx.x;   // BB*HIDN threads
    g_cp[i] = 0.f; g_ch[i] = 0.f; g_cm[i] = 0.f; g_hma[i] = 0.f;
}

// ------------------------- generic GEMM: C = A @ W^T (+b1+b2) [+=] ---------
// 64x64 output tile, BK=16, 256 threads, 4x4 register microtile.
// pairp != nullptr: A row m gathered from pair[b = m%64, l_off + m/64, :].
__global__ void gemm64(const float* __restrict__ A,
                       const float* __restrict__ pairp, int l_off,
                       const float* __restrict__ W,
                       const float* __restrict__ b1,
                       const float* __restrict__ b2,
                       float* __restrict__ C, int N, int K, int accum) {
    __shared__ __align__(16) float As[16][68];
    __shared__ __align__(16) float Bs[16][68];
    int tid = threadIdx.x;
    int n0 = blockIdx.x * 64, m0 = blockIdx.y * 64;
    int lr = tid >> 2;
    int lc = (tid & 3) * 4;
    const float* arow;
    {
        int m = m0 + lr;
        if (pairp) {
            int t = m >> 6, b = m & 63;
            arow = pairp + ((size_t)b * LL + l_off + t) * EMBD;
        } else {
            arow = A + (size_t)m * K;
        }
    }
    const float* wrow = W + (size_t)(n0 + lr) * K;
    int ty = tid >> 4, txx = tid & 15;
    float acc[4][4];
    #pragma unroll
    for (int i = 0; i < 4; i++)
        #pragma unroll
        for (int j = 0; j < 4; j++) acc[i][j] = 0.f;

    for (int k0 = 0; k0 < K; k0 += 16) {
        float4 a4 = *(const float4*)(arow + k0 + lc);
        float4 b4 = *(const float4*)(wrow + k0 + lc);
        __syncthreads();
        As[lc+0][lr]=a4.x; As[lc+1][lr]=a4.y; As[lc+2][lr]=a4.z; As[lc+3][lr]=a4.w;
        Bs[lc+0][lr]=b4.x; Bs[lc+1][lr]=b4.y; Bs[lc+2][lr]=b4.z; Bs[lc+3][lr]=b4.w;
        __syncthreads();
        #pragma unroll
        for (int kk = 0; kk < 16; kk++) {
            float4 av = *(const float4*)&As[kk][ty * 4];
            float4 bv = *(const float4*)&Bs[kk][txx * 4];
            float am[4] = {av.x, av.y, av.z, av.w};
            float bm[4] = {bv.x, bv.y, bv.z, bv.w};
            #pragma unroll
            for (int i = 0; i < 4; i++)
                #pragma unroll
                for (int j = 0; j < 4; j++)
                    acc[i][j] = fmaf(am[i], bm[j], acc[i][j]);
        }
    }
    #pragma unroll
    for (int i = 0; i < 4; i++) {
        int m = m0 + ty * 4 + i;
        #pragma unroll
        for (int j = 0; j < 4; j++) {
            int n = n0 + txx * 4 + j;
            float v = acc[i][j];
            if (b1) v += b1[n];
            if (b2) v += b2[n];
            if (accum) C[(size_t)m * N + n] += v;
            else       C[(size_t)m * N + n]  = v;
        }
    }
}

// ------------------------- fused LSTM step (premise + hypothesis) ----------
// grid (64, 2): y=0 premise, y=1 hypothesis. 256 threads; warp owns one d.
__global__ void lstm_step(int t, const float* __restrict__ Whh_p,
                          const float* __restrict__ Whh_h) {
    __shared__ float sh[64][65];
    int which = blockIdx.y;
    if (which == 1 && t >= THY) return;
    const float* Y   = which ? g_xh : g_xp;
    const float* Whh = which ? Whh_h : Whh_p;
    float* hsA = which ? g_ht : g_hs;
    float* cA  = which ? g_ch : g_cp;
    const float* hp = (t == 0) ? g_zero : (hsA + (size_t)(t - 1) * BB * HIDN);
    int tid  = threadIdx.x;
    int lane = tid & 31, w = tid >> 5;
    int d = blockIdx.x * 8 + w;

    float acc[2][4];
    #pragma unroll
    for (int g = 0; g < 4; g++) {
        int n = g * HIDN + d;
        acc[0][g] = Y[((size_t)t * BB + lane) * G4 + n];
        acc[1][g] = Y[((size_t)t * BB + lane + 32) * G4 + n];
    }
    const float* wr[4];
    #pragma unroll
    for (int g = 0; g < 4; g++) wr[g] = Whh + (size_t)(g * HIDN + d) * HIDN;

    for (int k0 = 0; k0 < HIDN; k0 += 64) {
        __syncthreads();
        load_tile64(sh, hp, HIDN, k0, tid);
        __syncthreads();
        #pragma unroll 8
        for (int kk = 0; kk < 64; kk++) {
            float hA = sh[lane][kk], hB = sh[lane + 32][kk];
            #pragma unroll
            for (int g = 0; g < 4; g++) {
                float wv = wr[g][k0 + kk];
                acc[0][g] = fmaf(wv, hA, acc[0][g]);
                acc[1][g] = fmaf(wv, hB, acc[1][g]);
            }
        }
    }
    #pragma unroll
    for (int bb = 0; bb < 2; bb++) {
        int b = lane + bb * 32;
        float ig = sig_fast(acc[bb][0]);
        float fg = sig_fast(acc[bb][1]);
        float gg = tanh_fast(acc[bb][2]);
        float og = sig_fast(acc[bb][3]);
        float c  = cA[b * HIDN + d];
        c = fg * c + ig * gg;
        cA[b * HIDN + d] = c;
        hsA[((size_t)t * BB + b) * HIDN + d] = og * tanh_fast(c);
    }
}

// ------------------------- match: u = Wt h_t_k + Wm h_m --------------------
// grid 64 CTAs x 256 thr; warp owns one output column n.
__global__ void match_u(int k, const float* __restrict__ Wm) {
    __shared__ float sh[64][65];
    const float* hmin = (k & 1) ? g_hmb : g_hma;
    int tid  = threadIdx.x;
    int lane = tid & 31, w = tid >> 5;
    int n = blockIdx.x * 8 + w;
    const float* wrow = Wm + (size_t)n * HIDN;
    float a0 = 0.f, a1 = 0.f;
    for (int k0 = 0; k0 < HIDN; k0 += 64) {
        __syncthreads();
        load_tile64(sh, hmin, HIDN, k0, tid);
        __syncthreads();
        #pragma unroll 8
        for (int kk = 0; kk < 64; kk++) {
            float wv = wrow[k0 + kk];
            a0 = fmaf(wv, sh[lane][kk], a0);
            a1 = fmaf(wv, sh[lane + 32][kk], a1);
        }
    }
    g_u[lane * HIDN + n]        = g_wtht[((size_t)k * BB + lane) * HIDN + n] + a0;
    g_u[(lane + 32) * HIDN + n] = g_wtht[((size_t)k * BB + lane + 32) * HIDN + n] + a1;
}

// ------------------------- match: attention + m_k --------------------------
// One CTA per batch element b, 512 threads.
__global__ void match_attn(int k, const float* __restrict__ w_e) {
    __shared__ float su[HIDN], swe[HIDN];
    __shared__ float se[TP];
    int b = blockIdx.x, tid = threadIdx.x;
    su[tid]  = g_u[b * HIDN + tid];
    swe[tid] = w_e[tid];
    __syncthreads();
    int lane = tid & 31, w = tid >> 5;          // 16 warps
    for (int j = w; j < TP; j += 16) {
        const float* row = g_wshs + ((size_t)j * BB + b) * HIDN;
        float p = 0.f;
        #pragma unroll 4
        for (int h = lane; h < HIDN; h += 32)
            p = fmaf(tanh_fast(row[h] + su[h]), swe[h], p);
        #pragma unroll
        for (int off = 16; off; off >>= 1)
            p += __shfl_xor_sync(0xffffffffu, p, off);
        if (lane == 0) se[j] = p;
    }
    __syncthreads();
    if (tid == 0) {                              // softmax over 65 (serial, tiny)
        float mx = se[0];
        for (int j = 1; j < TP; j++) mx = fmaxf(mx, se[j]);
        float s = 0.f;
        for (int j = 0; j < TP; j++) { float e = __expf(se[j] - mx); se[j] = e; s += e; }
        float inv = __fdividef(1.f, s);
        for (int j = 0; j < TP; j++) se[j] *= inv;
    }
    __syncthreads();
    float a = 0.f;                               // a_k[b, tid]
    #pragma unroll 5
    for (int j = 0; j < TP; j++)
        a = fmaf(se[j], g_hs[((size_t)j * BB + b) * HIDN + tid], a);
    g_mk[(size_t)b * 2 * HIDN + tid]        = a;
    g_mk[(size_t)b * 2 * HIDN + HIDN + tid] = g_ht[((size_t)k * BB + b) * HIDN + tid];
}

// ------------------------- match cell gate epilogue ------------------------
__global__ void cell_gates(int k) {
    int idx = blockIdx.x * blockDim.x + threadIdx.x;  // BB*HIDN threads
    int b = idx >> 9, d = idx & 511;
    float* hmout = (k & 1) ? g_hma : g_hmb;
    const float* g = g_gm + (size_t)b * G4;
    float ig = sig_fast(g[d]);
    float fg = sig_fast(g[HIDN + d]);
    float gg = tanh_fast(g[2 * HIDN + d]);
    float og = sig_fast(g[3 * HIDN + d]);
    float c  = g_cm[idx];
    c = fg * c + ig * gg;
    g_cm[idx] = c;
    hmout[idx] = og * tanh_fast(c);
}

// ------------------------- final classifier --------------------------------
// grid 64 (b), block 96: warp = class c.
__global__ void fc_out(const float* __restrict__ fc_w,
                       const float* __restrict__ fc_b,
                       float* __restrict__ out) {
    int b = blockIdx.x;
    int lane = threadIdx.x & 31, c = threadIdx.x >> 5;
    const float* hm = g_hma + (size_t)b * HIDN;      // final h_m (k=63 odd -> hma)
    const float* wr = fc_w + (size_t)c * HIDN;
    float p = 0.f;
    #pragma unroll 4
    for (int h = lane; h < HIDN; h += 32) p = fmaf(hm[h], wr[h], p);
    #pragma unroll
    for (int off = 16; off; off >>= 1) p += __shfl_xor_sync(0xffffffffu, p, off);
    if (lane == 0) out[b * 3 + c] = p + fc_b[c];
}

// ---------------------------------------------------------------------------
extern "C" void kernel_launch(void* const* d_in, const int* in_sizes, int n_in,
                              void* d_out, int out_size) {
    const float* pair  = (const float*)d_in[0];
    const float* w_e   = (const float*)d_in[3];
    const float* Ws    = (const float*)d_in[4];
    const float* Wt    = (const float*)d_in[5];
    const float* Wm    = (const float*)d_in[6];
    const float* fc_w  = (const float*)d_in[7];
    const float* fc_b  = (const float*)d_in[8];
    const float* Wih_p = (const float*)d_in[9];
    const float* Whh_p = (const float*)d_in[10];
    const float* bih_p = (const float*)d_in[11];
    const float* bhh_p = (const float*)d_in[12];
    const float* Wih_h = (const float*)d_in[13];
    const float* Whh_h = (const float*)d_in[14];
    const float* bih_h = (const float*)d_in[15];
    const float* bhh_h = (const float*)d_in[16];
    const float* Wih_m = (const float*)d_in[17];
    const float* Whh_m = (const float*)d_in[18];
    const float* bih_m = (const float*)d_in[19];
    const float* bhh_m = (const float*)d_in[20];
    float* out = (float*)d_out;

    // device addresses of scratch symbols (query only; no allocation)
    float *p_xp, *p_xh, *p_hs, *p_ht, *p_wshs, *p_wtht, *p_mk, *p_gm, *p_hma, *p_hmb;
    cudaGetSymbolAddress((void**)&p_xp,   g_xp);
    cudaGetSymbolAddress((void**)&p_xh,   g_xh);
    cudaGetSymbolAddress((void**)&p_hs,   g_hs);
    cudaGetSymbolAddress((void**)&p_ht,   g_ht);
    cudaGetSymbolAddress((void**)&p_wshs, g_wshs);
    cudaGetSymbolAddress((void**)&p_wtht, g_wtht);
    cudaGetSymbolAddress((void**)&p_mk,   g_mk);
    cudaGetSymbolAddress((void**)&p_gm,   g_gm);
    cudaGetSymbolAddress((void**)&p_hma,  g_hma);
    cudaGetSymbolAddress((void**)&p_hmb,  g_hmb);

    kinit<<<BB * HIDN / 256, 256>>>();

    // input preactivations: x @ Wih^T + bih + bhh
    gemm64<<<dim3(G4 / 64, TP),  256>>>(nullptr, pair, 1,  Wih_p, bih_p, bhh_p,
                                        p_xp, G4, EMBD, 0);
    gemm64<<<dim3(G4 / 64, THY), 256>>>(nullptr, pair, 2 + 64, Wih_h, bih_h, bhh_h,
                                        p_xh, G4, EMBD, 0);

    // both recurrences, fused per step
    for (int t = 0; t < TP; t++)
        lstm_step<<<dim3(64, 2), 256>>>(t, Whh_p, Whh_h);

    // attention precompute: Ws@h_s, Wt@h_t
    gemm64<<<dim3(HIDN / 64, TP),  256>>>(p_hs, nullptr, 0, Ws, nullptr, nullptr,
                                          p_wshs, HIDN, HIDN, 0);
    gemm64<<<dim3(HIDN / 64, THY), 256>>>(p_ht, nullptr, 0, Wt, nullptr, nullptr,
                                          p_wtht, HIDN, HIDN, 0);

    // match loop
    for (int k = 0; k < THY; k++) {
        const float* hmin = (k & 1) ? p_hmb : p_hma;
        match_u<<<64, 256>>>(k, Wm);
        match_attn<<<64, 512>>>(k, w_e);
        gemm64<<<dim3(G4 / 64, 1), 256>>>(p_mk, nullptr, 0, Wih_m, bih_m, bhh_m,
                                          p_gm, G4, 2 * HIDN, 0);
        gemm64<<<dim3(G4 / 64, 1), 256>>>(hmin, nullptr, 0, Whh_m, nullptr, nullptr,
                                          p_gm, G4, HIDN, 1);
        cell_gates<<<BB * HIDN / 256, 256>>>(k);
    }

    fc_out<<<64, 96>>>(fc_w, fc_b, out);
}

// round 3
// speedup vs baseline: 1.7972x; 1.7972x over previous
#include <cuda_runtime.h>

// ---------------------------------------------------------------------------
// MatchLSTM: B=64, premise steps TP=65, hyp THY=64, EMB=768, HID=512
// Round 2: persistent recurrent kernels (smem-resident weights, grid barriers)
//          + hoisted Wih_m_right @ h_t + 128x64 fp32 GEMM tile.
// ---------------------------------------------------------------------------
#define BB    64
#define TP    65
#define THY   64
#define HIDN  512
#define G4    2048
#define EMBD  768
#define LL    130

// ------------------------- device scratch (no allocs) ----------------------
__device__ float g_xp[TP * BB * G4];
__device__ float g_xh[THY * BB * G4];
__device__ float g_xhm[THY * BB * G4];            // xh_m = WihR@h_t + biases
__device__ float g_hs[TP * BB * HIDN];
__device__ float g_ht[THY * BB * HIDN];
__device__ float g_wshs[TP * BB * HIDN];
__device__ float g_wtht[THY * BB * HIDN];
__device__ float g_ak[THY * BB * HIDN];           // a_k per step
__device__ float g_hm[(THY + 1) * BB * HIDN];     // slot 0 never written = 0
__device__ float g_wmhm[(THY + 1) * BB * HIDN];   // Wm @ h_m, slot 0 unused
__device__ unsigned g_ctr[8];                     // barrier counters

// ------------------------- activations (MUFU-based) ------------------------
__device__ __forceinline__ float sigm(float x) {
    return __fdividef(1.f, 1.f + __expf(-x));
}
__device__ __forceinline__ float tanhm(float x) {
    return __fdividef(2.f, 1.f + __expf(-2.f * x)) - 1.f;
}

// ------------------------- grid-group barrier ------------------------------
// All CTAs of the group call with identical monotonically increasing
// 'expected' = group_size * phase. Counter zeroed by kinit each launch.
__device__ __forceinline__ void gbar(unsigned* ctr, unsigned expected) {
    __threadfence();
    __syncthreads();
    if (threadIdx.x == 0) {
        atomicAdd(ctr, 1u);
        while (*(volatile unsigned*)ctr < expected) { __nanosleep(32); }
        __threadfence();
    }
    __syncthreads();
}

__global__ void kinit() {
    if (threadIdx.x < 8) g_ctr[threadIdx.x] = 0;
}

// ------------------------- 64x64 tile stage (256 thr) ----------------------
// dst[64][68] <- src rows 0..63 (row stride 512), cols k0..k0+63
__device__ __forceinline__ void ldtile(float (*tile)[68],
                                       const float* __restrict__ src,
                                       int k0, int tid) {
    int bl = tid >> 2, ks = (tid & 3) * 16;
    const float4* s = (const float4*)(src + (size_t)bl * HIDN + k0 + ks);
    float4 a = s[0], b = s[1], c = s[2], d = s[3];
    *(float4*)&tile[bl][ks]      = a;
    *(float4*)&tile[bl][ks + 4]  = b;
    *(float4*)&tile[bl][ks + 8]  = c;
    *(float4*)&tile[bl][ks + 12] = d;
}

// ------------------------- parallel GEMM: C = A @ W^T (+b1+b2) -------------
// 128x64 tile, BK=16, 256 threads, 8x4 microtile. W row-major [N, ldw],
// columns woff..woff+K used. pairp: gather A rows from pair tensor.
__global__ void gemm128(const float* __restrict__ A, int lda,
                        const float* __restrict__ pairp, int l_off,
                        const float* __restrict__ W, int ldw, int woff,
                        const float* __restrict__ b1, const float* __restrict__ b2,
                        float* __restrict__ C, int M, int N, int K) {
    __shared__ __align__(16) float As[128][20];
    __shared__ __align__(16) float Bs[16][68];
    int tid = threadIdx.x;
    int m0 = blockIdx.y * 128, n0 = blockIdx.x * 64;
    // A loader: row m0 + tid/2, k-slot (tid&1)*8
    const float* arow;
    {
        int m = m0 + (tid >> 1);
        if (m >= M) m = 0;
        if (pairp) {
            int t = m >> 6, b = m & 63;
            arow = pairp + ((size_t)b * LL + l_off + t) * EMBD;
        } else {
            arow = A + (size_t)m * lda;
        }
    }
    int aki = (tid & 1) * 8;
    const float* wrow = W + (size_t)(n0 + (tid >> 2)) * ldw + woff;
    int bki = (tid & 3) * 4;
    int ty = tid >> 4, tx = tid & 15;

    float acc[8][4];
    #pragma unroll
    for (int i = 0; i < 8; i++)
        #pragma unroll
        for (int j = 0; j < 4; j++) acc[i][j] = 0.f;

    for (int k0 = 0; k0 < K; k0 += 16) {
        float4 a0 = *(const float4*)(arow + k0 + aki);
        float4 a1 = *(const float4*)(arow + k0 + aki + 4);
        float4 bv = *(const float4*)(wrow + k0 + bki);
        __syncthreads();
        *(float4*)&As[tid >> 1][aki]     = a0;
        *(float4*)&As[tid >> 1][aki + 4] = a1;
        Bs[bki + 0][tid >> 2] = bv.x;
        Bs[bki + 1][tid >> 2] = bv.y;
        Bs[bki + 2][tid >> 2] = bv.z;
        Bs[bki + 3][tid >> 2] = bv.w;
        __syncthreads();
        #pragma unroll
        for (int kk = 0; kk < 16; kk++) {
            float bm[4];
            float4 bv4 = *(const float4*)&Bs[kk][tx * 4];
            bm[0] = bv4.x; bm[1] = bv4.y; bm[2] = bv4.z; bm[3] = bv4.w;
            #pragma unroll
            for (int i = 0; i < 8; i++) {
                float av = As[ty * 8 + i][kk];
                #pragma unroll
                for (int j = 0; j < 4; j++)
                    acc[i][j] = fmaf(av, bm[j], acc[i][j]);
            }
        }
    }
    #pragma unroll
    for (int i = 0; i < 8; i++) {
        int m = m0 + ty * 8 + i;
        if (m >= M) continue;
        #pragma unroll
        for (int j = 0; j < 4; j++) {
            int n = n0 + tx * 4 + j;
            float v = acc[i][j];
            if (b1) v += b1[n];
            if (b2) v += b2[n];
            C[(size_t)m * N + n] = v;
        }
    }
}

// ------------------------- persistent dual LSTM ----------------------------
// 128 CTAs x 256 thr. CTA c: which = c>>6 (0 premise / 1 hyp), owns 8 d.
// Weights (32 gate-rows x 512) resident in smem; c-state in registers.
__global__ void lstm_pers(const float* __restrict__ Whh_p,
                          const float* __restrict__ Whh_h) {
    extern __shared__ float sm[];
    float* wsm = sm;                              // 32*512
    float (*tile)[68] = (float(*)[68])(sm + 32 * 512);
    int cta = blockIdx.x;
    int which = cta >> 6;
    int dblk = cta & 63;
    const float* Whh = which ? Whh_h : Whh_p;
    const float* Y   = which ? g_xh : g_xp;
    float* hout      = which ? g_ht : g_hs;
    unsigned* ctr = &g_ctr[which];
    int steps = which ? THY : TP;
    int tid = threadIdx.x, lane = tid & 31, w = tid >> 5;
    int d = dblk * 8 + w;

    // stage weights: wsm[(dl*4+g)*512 + k] = Whh[g*512 + dblk*8+dl][k]
    for (int i4 = tid; i4 < 4096; i4 += 256) {
        int idx = i4 * 4;
        int r = idx >> 9, k = idx & 511;
        int dl = r >> 2, g = r & 3;
        *(float4*)&wsm[idx] =
            *(const float4*)&Whh[((size_t)(g * 512 + dblk * 8 + dl)) * 512 + k];
    }
    __syncthreads();

    float c0 = 0.f, c1 = 0.f;
    for (int t = 0; t < steps; t++) {
        float acc[2][4];
        #pragma unroll
        for (int g = 0; g < 4; g++) {
            acc[0][g] = Y[((size_t)t * BB + lane) * G4 + g * 512 + d];
            acc[1][g] = Y[((size_t)t * BB + lane + 32) * G4 + g * 512 + d];
        }
        if (t > 0) {
            gbar(ctr, 64u * (unsigned)t);
            const float* hp = hout + (size_t)(t - 1) * BB * HIDN;
            for (int k0 = 0; k0 < HIDN; k0 += 64) {
                __syncthreads();
                ldtile(tile, hp, k0, tid);
                __syncthreads();
                #pragma unroll
                for (int kk = 0; kk < 64; kk += 4) {
                    float4 hA = *(const float4*)&tile[lane][kk];
                    float4 hB = *(const float4*)&tile[lane + 32][kk];
                    #pragma unroll
                    for (int g = 0; g < 4; g++) {
                        float4 wv = *(const float4*)&wsm[(w * 4 + g) * 512 + k0 + kk];
                        acc[0][g] = fmaf(wv.x, hA.x, acc[0][g]);
                        acc[0][g] = fmaf(wv.y, hA.y, acc[0][g]);
                        acc[0][g] = fmaf(wv.z, hA.z, acc[0][g]);
                        acc[0][g] = fmaf(wv.w, hA.w, acc[0][g]);
                        acc[1][g] = fmaf(wv.x, hB.x, acc[1][g]);
                        acc[1][g] = fmaf(wv.y, hB.y, acc[1][g]);
                        acc[1][g] = fmaf(wv.z, hB.z, acc[1][g]);
                        acc[1][g] = fmaf(wv.w, hB.w, acc[1][g]);
                    }
                }
            }
        }
        float ig, fg, gg, og;
        ig = sigm(acc[0][0]); fg = sigm(acc[0][1]);
        gg = tanhm(acc[0][2]); og = sigm(acc[0][3]);
        c0 = fg * c0 + ig * gg;
        hout[((size_t)t * BB + lane) * HIDN + d] = og * tanhm(c0);
        ig = sigm(acc[1][0]); fg = sigm(acc[1][1]);
        gg = tanhm(acc[1][2]); og = sigm(acc[1][3]);
        c1 = fg * c1 + ig * gg;
        hout[((size_t)t * BB + lane + 32) * HIDN + d] = og * tanhm(c1);
    }
}

// ------------------------- persistent match loop ---------------------------
// 128 CTAs x 256 thr. Per step: A(attention, CTAs 0-63, CTA=b) | bar |
// B(cell GEMM K=1024, CTA owns 4 d, weights in smem, c in regs) | bar |
// D(wmhm[k+1] = Wm @ h_m[k], CTA owns 4 n) | bar.
__global__ void match_pers(const float* __restrict__ Wih_m,
                           const float* __restrict__ Whh_m,
                           const float* __restrict__ Wm,
                           const float* __restrict__ w_e) {
    extern __shared__ float sm[];
    float* wcat = sm;                              // 16*1024
    float* wm_s = sm + 16 * 1024;                  // 4*512
    float (*tile)[68] = (float(*)[68])(wm_s + 4 * 512);
    float* su  = (float*)(tile + 64);              // 512
    float* swe = su + 512;                         // 512
    float* se  = swe + 512;                        // 96
    int cta = blockIdx.x;
    int tid = threadIdx.x, lane = tid & 31, w = tid >> 5;

    // cell weights: wcat[(dl*4+g)*1024 + k] = [WihL | Whh] row g*512 + cta*4+dl
    for (int i4 = tid; i4 < 4096; i4 += 256) {
        int idx = i4 * 4;
        int r = idx >> 10, k = idx & 1023;
        int dl = r >> 2, g = r & 3;
        int grow = g * 512 + cta * 4 + dl;
        float4 v = (k < 512)
            ? *(const float4*)&Wih_m[(size_t)grow * 1024 + k]
            : *(const float4*)&Whh_m[(size_t)grow * 512 + (k - 512)];
        *(float4*)&wcat[idx] = v;
    }
    // Wm rows (for D): n = cta*4 + nl
    for (int i4 = tid; i4 < 512; i4 += 256) {
        int idx = i4 * 4;
        int nl = idx >> 9, k = idx & 511;
        *(float4*)&wm_s[idx] = *(const float4*)&Wm[(size_t)(cta * 4 + nl) * 512 + k];
    }
    __syncthreads();

    // B-phase mapping: b = (w>>2)*32 + lane, dloc = w&3; D: nl = tid>>6, bD = tid&63
    int bB = (w >> 2) * 32 + lane;
    int dloc = w & 3;
    int d = cta * 4 + dloc;
    int nl = tid >> 6, bD = tid & 63;
    float c_m = 0.f;
    unsigned ph = 0;

    for (int k = 0; k < THY; k++) {
        // ---- A: attention for batch b = cta (CTAs 0..63) ----
        if (cta < BB) {
            int b = cta;
            float w0 = (k > 0) ? g_wmhm[((size_t)k * BB + b) * HIDN + tid] : 0.f;
            float w1 = (k > 0) ? g_wmhm[((size_t)k * BB + b) * HIDN + tid + 256] : 0.f;
            su[tid]       = g_wtht[((size_t)k * BB + b) * HIDN + tid] + w0;
            su[tid + 256] = g_wtht[((size_t)k * BB + b) * HIDN + tid + 256] + w1;
            swe[tid]       = w_e[tid];
            swe[tid + 256] = w_e[tid + 256];
            __syncthreads();
            for (int j = w; j < TP; j += 8) {
                const float* row = g_wshs + ((size_t)j * BB + b) * HIDN;
                float p = 0.f;
                #pragma unroll 4
                for (int h = lane; h < HIDN; h += 32)
                    p = fmaf(tanhm(row[h] + su[h]), swe[h], p);
                #pragma unroll
                for (int off = 16; off; off >>= 1)
                    p += __shfl_xor_sync(0xffffffffu, p, off);
                if (lane == 0) se[j] = p;
            }
            __syncthreads();
            if (w == 0) {           // softmax over 65
                float v0 = se[lane], v1 = se[lane + 32];
                float v2 = (lane == 0) ? se[64] : -1e30f;
                float mx = fmaxf(fmaxf(v0, v1), v2);
                #pragma unroll
                for (int off = 16; off; off >>= 1)
                    mx = fmaxf(mx, __shfl_xor_sync(0xffffffffu, mx, off));
                float e0 = __expf(v0 - mx), e1 = __expf(v1 - mx);
                float e2 = (lane == 0) ? __expf(v2 - mx) : 0.f;
                float s = e0 + e1 + e2;
                #pragma unroll
                for (int off = 16; off; off >>= 1)
                    s += __shfl_xor_sync(0xffffffffu, s, off);
                float inv = __fdividef(1.f, s);
                se[lane] = e0 * inv; se[lane + 32] = e1 * inv;
                if (lane == 0) se[64] = e2 * inv;
            }
            __syncthreads();
            float a0 = 0.f, a1 = 0.f;
            #pragma unroll 5
            for (int j = 0; j < TP; j++) {
                float al = se[j];
                const float* hr = g_hs + ((size_t)j * BB + b) * HIDN;
                a0 = fmaf(al, hr[tid], a0);
                a1 = fmaf(al, hr[tid + 256], a1);
            }
            g_ak[((size_t)k * BB + b) * HIDN + tid]       = a0;
            g_ak[((size_t)k * BB + b) * HIDN + tid + 256] = a1;
        }
        gbar(&g_ctr[2], 128u * (++ph));

        // ---- B: cell GEMM + gates ----
        float acc[4];
        #pragma unroll
        for (int g = 0; g < 4; g++)
            acc[g] = g_xhm[((size_t)k * BB + bB) * G4 + g * 512 + d];
        const float* a_in = g_ak + (size_t)k * BB * HIDN;
        const float* h_in = g_hm + (size_t)k * BB * HIDN;
        for (int k0 = 0; k0 < 1024; k0 += 64) {
            const float* src = (k0 < 512) ? (a_in + k0) : (h_in + k0 - 512);
            __syncthreads();
            ldtile(tile, src, 0, tid);
            __syncthreads();
            #pragma unroll
            for (int kk = 0; kk < 64; kk += 4) {
                float4 hv = *(const float4*)&tile[bB][kk];
                #pragma unroll
                for (int g = 0; g < 4; g++) {
                    float4 wv = *(const float4*)&wcat[(dloc * 4 + g) * 1024 + k0 + kk];
                    acc[g] = fmaf(wv.x, hv.x, acc[g]);
                    acc[g] = fmaf(wv.y, hv.y, acc[g]);
                    acc[g] = fmaf(wv.z, hv.z, acc[g]);
                    acc[g] = fmaf(wv.w, hv.w, acc[g]);
                }
            }
        }
        {
            float ig = sigm(acc[0]), fg = sigm(acc[1]);
            float gg = tanhm(acc[2]), og = sigm(acc[3]);
            c_m = fg * c_m + ig * gg;
            g_hm[((size_t)(k + 1) * BB + bB) * HIDN + d] = og * tanhm(c_m);
        }
        gbar(&g_ctr[2], 128u * (++ph));

        // ---- D: wmhm[k+1] = Wm @ h_m[k+1-th slot] ----
        {
            const float* hmk = g_hm + (size_t)(k + 1) * BB * HIDN;
            float s = 0.f;
            for (int k0 = 0; k0 < HIDN; k0 += 64) {
                __syncthreads();
                ldtile(tile, hmk, k0, tid);
                __syncthreads();
                #pragma unroll
                for (int kk = 0; kk < 64; kk += 4) {
                    float4 hv = *(const float4*)&tile[bD][kk];
                    float4 wv = *(const float4*)&wm_s[nl * 512 + k0 + kk];
                    s = fmaf(wv.x, hv.x, s);
                    s = fmaf(wv.y, hv.y, s);
                    s = fmaf(wv.z, hv.z, s);
                    s = fmaf(wv.w, hv.w, s);
                }
            }
            g_wmhm[((size_t)(k + 1) * BB + bD) * HIDN + cta * 4 + nl] = s;
        }
        if (k < THY - 1) gbar(&g_ctr[2], 128u * (++ph));
    }
}

// ------------------------- final classifier --------------------------------
__global__ void fc_out(const float* __restrict__ fc_w,
                       const float* __restrict__ fc_b,
                       float* __restrict__ out) {
    int b = blockIdx.x;
    int lane = threadIdx.x & 31, c = threadIdx.x >> 5;
    const float* hm = g_hm + (size_t)THY * BB * HIDN + (size_t)b * HIDN;
    const float* wr = fc_w + (size_t)c * HIDN;
    float p = 0.f;
    #pragma unroll 4
    for (int h = lane; h < HIDN; h += 32) p = fmaf(hm[h], wr[h], p);
    #pragma unroll
    for (int off = 16; off; off >>= 1) p += __shfl_xor_sync(0xffffffffu, p, off);
    if (lane == 0) out[b * 3 + c] = p + fc_b[c];
}

// ---------------------------------------------------------------------------
extern "C" void kernel_launch(void* const* d_in, const int* in_sizes, int n_in,
                              void* d_out, int out_size) {
    const float* pair  = (const float*)d_in[0];
    const float* w_e   = (const float*)d_in[3];
    const float* Ws    = (const float*)d_in[4];
    const float* Wt    = (const float*)d_in[5];
    const float* Wm    = (const float*)d_in[6];
    const float* fc_w  = (const float*)d_in[7];
    const float* fc_b  = (const float*)d_in[8];
    const float* Wih_p = (const float*)d_in[9];
    const float* Whh_p = (const float*)d_in[10];
    const float* bih_p = (const float*)d_in[11];
    const float* bhh_p = (const float*)d_in[12];
    const float* Wih_h = (const float*)d_in[13];
    const float* Whh_h = (const float*)d_in[14];
    const float* bih_h = (const float*)d_in[15];
    const float* bhh_h = (const float*)d_in[16];
    const float* Wih_m = (const float*)d_in[17];
    const float* Whh_m = (const float*)d_in[18];
    const float* bih_m = (const float*)d_in[19];
    const float* bhh_m = (const float*)d_in[20];
    float* out = (float*)d_out;

    float *p_xp, *p_xh, *p_xhm, *p_hs, *p_ht, *p_wshs, *p_wtht;
    cudaGetSymbolAddress((void**)&p_xp,   g_xp);
    cudaGetSymbolAddress((void**)&p_xh,   g_xh);
    cudaGetSymbolAddress((void**)&p_xhm,  g_xhm);
    cudaGetSymbolAddress((void**)&p_hs,   g_hs);
    cudaGetSymbolAddress((void**)&p_ht,   g_ht);
    cudaGetSymbolAddress((void**)&p_wshs, g_wshs);
    cudaGetSymbolAddress((void**)&p_wtht, g_wtht);

    static int smem_set = 0;
    int lstm_smem  = (32 * 512 + 64 * 68) * 4;
    int match_smem = (16 * 1024 + 4 * 512 + 64 * 68 + 512 + 512 + 96) * 4;
    if (!smem_set) {
        cudaFuncSetAttribute(lstm_pers,
            cudaFuncAttributeMaxDynamicSharedMemorySize, lstm_smem);
        cudaFuncSetAttribute(match_pers,
            cudaFuncAttributeMaxDynamicSharedMemorySize, match_smem);
        smem_set = 1;
    }

    kinit<<<1, 32>>>();

    // input preactivations (biases folded)
    gemm128<<<dim3(G4 / 64, (TP * BB + 127) / 128), 256>>>(
        nullptr, 0, pair, 1, Wih_p, EMBD, 0, bih_p, bhh_p,
        p_xp, TP * BB, G4, EMBD);
    gemm128<<<dim3(G4 / 64, (THY * BB) / 128), 256>>>(
        nullptr, 0, pair, 2 + 64, Wih_h, EMBD, 0, bih_h, bhh_h,
        p_xh, THY * BB, G4, EMBD);

    // both LSTM recurrences in one persistent kernel
    lstm_pers<<<128, 256, lstm_smem>>>(Whh_p, Whh_h);

    // attention precomputes + hoisted match-cell input half
    gemm128<<<dim3(HIDN / 64, (TP * BB + 127) / 128), 256>>>(
        p_hs, HIDN, nullptr, 0, Ws, HIDN, 0, nullptr, nullptr,
        p_wshs, TP * BB, HIDN, HIDN);
    gemm128<<<dim3(HIDN / 64, (THY * BB) / 128), 256>>>(
        p_ht, HIDN, nullptr, 0, Wt, HIDN, 0, nullptr, nullptr,
        p_wtht, THY * BB, HIDN, HIDN);
    gemm128<<<dim3(G4 / 64, (THY * BB) / 128), 256>>>(
        p_ht, HIDN, nullptr, 0, Wih_m, 2 * HIDN, HIDN, bih_m, bhh_m,
        p_xhm, THY * BB, G4, HIDN);

    // full match loop in one persistent kernel
    match_pers<<<128, 256, match_smem>>>(Wih_m, Whh_m, Wm, w_e);

    fc_out<<<64, 96>>>(fc_w, fc_b, out);
}

// round 4
// speedup vs baseline: 1.9089x; 1.0622x over previous
#include <cuda_runtime.h>
#include <cuda_bf16.h>

// ---------------------------------------------------------------------------
// MatchLSTM: B=64, premise steps TP=65, hyp THY=64, EMB=768, HID=512
// Round 4: bf16-split mma.sync for parallel GEMMs + fma.rn.f32x2 packed FMA
//          in persistent recurrent kernels.
// ---------------------------------------------------------------------------
#define BB    64
#define TP    65
#define THY   64
#define HIDN  512
#define G4    2048
#define EMBD  768
#define LL    130

typedef unsigned long long ull;

// ------------------------- device scratch (no allocs) ----------------------
__device__ float g_xp[TP * BB * G4];
__device__ float g_xh[THY * BB * G4];
__device__ float g_xhm[THY * BB * G4];
__device__ float g_hs[TP * BB * HIDN];
__device__ float g_ht[THY * BB * HIDN];
__device__ float g_wshs[TP * BB * HIDN];
__device__ float g_wtht[THY * BB * HIDN];
__device__ float g_ak[THY * BB * HIDN];
__device__ float g_hm[(THY + 1) * BB * HIDN];     // slot 0 never written = 0
__device__ float g_wmhm[(THY + 1) * BB * HIDN];
__device__ unsigned g_ctr[8];

// ------------------------- packed f32x2 FMA --------------------------------
__device__ __forceinline__ void dfma(ull& c, ull a, ull b) {
    asm("fma.rn.f32x2 %0, %1, %2, %0;" : "+l"(c) : "l"(a), "l"(b));
}
__device__ __forceinline__ float dred(ull c) {
    float2 f = *(float2*)&c;
    return f.x + f.y;
}
__device__ __forceinline__ ull dpack(float x, float y) {
    float2 f = make_float2(x, y);
    return *(ull*)&f;
}

// ------------------------- activations (MUFU-based) ------------------------
__device__ __forceinline__ float sigm(float x) {
    return __fdividef(1.f, 1.f + __expf(-x));
}
__device__ __forceinline__ float tanhm(float x) {
    return __fdividef(2.f, 1.f + __expf(-2.f * x)) - 1.f;
}

// ------------------------- grid-group barrier ------------------------------
__device__ __forceinline__ void gbar(unsigned* ctr, unsigned expected) {
    __threadfence();
    __syncthreads();
    if (threadIdx.x == 0) {
        atomicAdd(ctr, 1u);
        while (*(volatile unsigned*)ctr < expected) { __nanosleep(32); }
        __threadfence();
    }
    __syncthreads();
}

__global__ void kinit() {
    if (threadIdx.x < 8) g_ctr[threadIdx.x] = 0;
}

// ------------------------- 64x64 tile stage (256 thr) ----------------------
__device__ __forceinline__ void ldtile(float (*tile)[68],
                                       const float* __restrict__ src,
                                       int k0, int tid) {
    int bl = tid >> 2, ks = (tid & 3) * 16;
    const float4* s = (const float4*)(src + (size_t)bl * HIDN + k0 + ks);
    float4 a = s[0], b = s[1], c = s[2], d = s[3];
    *(float4*)&tile[bl][ks]      = a;
    *(float4*)&tile[bl][ks + 4]  = b;
    *(float4*)&tile[bl][ks + 8]  = c;
    *(float4*)&tile[bl][ks + 12] = d;
}

// ------------------------- bf16-split tensor GEMM --------------------------
// C[M,N] = A[M,K] @ W[N, ldw ](cols woff..)^T + b1 + b2
// BM=128, BN=64, BK=16, 256 threads, warp grid 4(m) x 2(n), warp tile 32x32.
// pairp: gather A row m from pair[b=m%64, l_off+m/64, :].
#define APAD 24
__device__ __forceinline__ void bsplit(float x, __nv_bfloat16& h, __nv_bfloat16& l) {
    h = __float2bfloat16_rn(x);
    l = __float2bfloat16_rn(x - __bfloat162float(h));
}

__global__ void __launch_bounds__(256, 2)
gemm_mma(const float* __restrict__ A, int lda,
         const float* __restrict__ pairp, int l_off,
         const float* __restrict__ W, int ldw, int woff,
         const float* __restrict__ b1, const float* __restrict__ b2,
         float* __restrict__ C, int M, int N, int K) {
    __shared__ __nv_bfloat16 Ahi[128][APAD], Alo[128][APAD];
    __shared__ __nv_bfloat16 Bhi[64][APAD],  Blo[64][APAD];
    int tid = threadIdx.x, lane = tid & 31, wid = tid >> 5;
    int m0 = blockIdx.y * 128, n0 = blockIdx.x * 64;
    int wm = wid & 3, wn = wid >> 2;

    float acc[2][4][4];
    #pragma unroll
    for (int i = 0; i < 2; i++)
        #pragma unroll
        for (int j = 0; j < 4; j++)
            #pragma unroll
            for (int r = 0; r < 4; r++) acc[i][j][r] = 0.f;

    // staging indices: A -> 512 float4/iter (2 per thread); B -> 256 (1 each)
    int brow = tid >> 2, bc4 = tid & 3;
    const float* wrow = W + (size_t)(n0 + brow) * ldw + woff;

    for (int k0 = 0; k0 < K; k0 += 16) {
        __syncthreads();
        // ---- stage A
        #pragma unroll
        for (int j = 0; j < 2; j++) {
            int i4 = tid * 2 + j;
            int row = i4 >> 2, c4 = i4 & 3;
            int m = m0 + row;
            int mr = (m < M) ? m : 0;
            const float* arow;
            if (pairp) {
                int t = mr >> 6, b = mr & 63;
                arow = pairp + ((size_t)b * LL + l_off + t) * EMBD;
            } else {
                arow = A + (size_t)mr * lda;
            }
            float4 v = *(const float4*)(arow + k0 + c4 * 4);
            __nv_bfloat16 h0,l0,h1,l1,h2,l2,h3,l3;
            bsplit(v.x,h0,l0); bsplit(v.y,h1,l1); bsplit(v.z,h2,l2); bsplit(v.w,h3,l3);
            *(__nv_bfloat162*)&Ahi[row][c4*4]   = __nv_bfloat162(h0,h1);
            *(__nv_bfloat162*)&Ahi[row][c4*4+2] = __nv_bfloat162(h2,h3);
            *(__nv_bfloat162*)&Alo[row][c4*4]   = __nv_bfloat162(l0,l1);
            *(__nv_bfloat162*)&Alo[row][c4*4+2] = __nv_bfloat162(l2,l3);
        }
        // ---- stage B (W)
        {
            float4 v = *(const float4*)(wrow + k0 + bc4 * 4);
            __nv_bfloat16 h0,l0,h1,l1,h2,l2,h3,l3;
            bsplit(v.x,h0,l0); bsplit(v.y,h1,l1); bsplit(v.z,h2,l2); bsplit(v.w,h3,l3);
            *(__nv_bfloat162*)&Bhi[brow][bc4*4]   = __nv_bfloat162(h0,h1);
            *(__nv_bfloat162*)&Bhi[brow][bc4*4+2] = __nv_bfloat162(h2,h3);
            *(__nv_bfloat162*)&Blo[brow][bc4*4]   = __nv_bfloat162(l0,l1);
            *(__nv_bfloat162*)&Blo[brow][bc4*4+2] = __nv_bfloat162(l2,l3);
        }
        __syncthreads();

        // ---- fragments + mma
        int fr = lane >> 2, fc = (lane & 3) * 2;
        unsigned ah[2][4], al[2][4], bh[4][2], bl[4][2];
        #pragma unroll
        for (int mt = 0; mt < 2; mt++) {
            int mb = wm * 32 + mt * 16;
            ah[mt][0] = *(unsigned*)&Ahi[mb + fr][fc];
            ah[mt][1] = *(unsigned*)&Ahi[mb + fr + 8][fc];
            ah[mt][2] = *(unsigned*)&Ahi[mb + fr][fc + 8];
            ah[mt][3] = *(unsigned*)&Ahi[mb + fr + 8][fc + 8];
            al[mt][0] = *(unsigned*)&Alo[mb + fr][fc];
            al[mt][1] = *(unsigned*)&Alo[mb + fr + 8][fc];
            al[mt][2] = *(unsigned*)&Alo[mb + fr][fc + 8];
            al[mt][3] = *(unsigned*)&Alo[mb + fr + 8][fc + 8];
        }
        #pragma unroll
        for (int nt = 0; nt < 4; nt++) {
            int nb = wn * 32 + nt * 8;
            bh[nt][0] = *(unsigned*)&Bhi[nb + fr][fc];
            bh[nt][1] = *(unsigned*)&Bhi[nb + fr][fc + 8];
            bl[nt][0] = *(unsigned*)&Blo[nb + fr][fc];
            bl[nt][1] = *(unsigned*)&Blo[nb + fr][fc + 8];
        }
        #pragma unroll
        for (int mt = 0; mt < 2; mt++)
            #pragma unroll
            for (int nt = 0; nt < 4; nt++) {
                float* d = acc[mt][nt];
                asm("mma.sync.aligned.m16n8k16.row.col.f32.bf16.bf16.f32 "
                    "{%0,%1,%2,%3},{%4,%5,%6,%7},{%8,%9},{%0,%1,%2,%3};"
                    : "+f"(d[0]), "+f"(d[1]), "+f"(d[2]), "+f"(d[3])
                    : "r"(ah[mt][0]), "r"(ah[mt][1]), "r"(ah[mt][2]), "r"(ah[mt][3]),
                      "r"(bh[nt][0]), "r"(bh[nt][1]));
                asm("mma.sync.aligned.m16n8k16.row.col.f32.bf16.bf16.f32 "
                    "{%0,%1,%2,%3},{%4,%5,%6,%7},{%8,%9},{%0,%1,%2,%3};"
                    : "+f"(d[0]), "+f"(d[1]), "+f"(d[2]), "+f"(d[3])
                    : "r"(ah[mt][0]), "r"(ah[mt][1]), "r"(ah[mt][2]), "r"(ah[mt][3]),
                      "r"(bl[nt][0]), "r"(bl[nt][1]));
                asm("mma.sync.aligned.m16n8k16.row.col.f32.bf16.bf16.f32 "
                    "{%0,%1,%2,%3},{%4,%5,%6,%7},{%8,%9},{%0,%1,%2,%3};"
                    : "+f"(d[0]), "+f"(d[1]), "+f"(d[2]), "+f"(d[3])
                    : "r"(al[mt][0]), "r"(al[mt][1]), "r"(al[mt][2]), "r"(al[mt][3]),
                      "r"(bh[nt][0]), "r"(bh[nt][1]));
            }
    }

    // ---- epilogue
    int fr = lane >> 2, fc = (lane & 3) * 2;
    #pragma unroll
    for (int mt = 0; mt < 2; mt++) {
        #pragma unroll
        for (int nt = 0; nt < 4; nt++) {
            int n = n0 + wn * 32 + nt * 8 + fc;
            float bb0 = 0.f, bb1 = 0.f;
            if (b1) { bb0 += b1[n]; bb1 += b1[n + 1]; }
            if (b2) { bb0 += b2[n]; bb1 += b2[n + 1]; }
            int m = m0 + wm * 32 + mt * 16 + fr;
            if (m < M) {
                C[(size_t)m * N + n]     = acc[mt][nt][0] + bb0;
                C[(size_t)m * N + n + 1] = acc[mt][nt][1] + bb1;
            }
            if (m + 8 < M) {
                C[(size_t)(m + 8) * N + n]     = acc[mt][nt][2] + bb0;
                C[(size_t)(m + 8) * N + n + 1] = acc[mt][nt][3] + bb1;
            }
        }
    }
}

// ------------------------- persistent dual LSTM (f32x2) --------------------
__global__ void lstm_pers(const float* __restrict__ Whh_p,
                          const float* __restrict__ Whh_h) {
    extern __shared__ float sm[];
    float* wsm = sm;                              // 32*512
    float (*tile)[68] = (float(*)[68])(sm + 32 * 512);
    int cta = blockIdx.x;
    int which = cta >> 6;
    int dblk = cta & 63;
    const float* Whh = which ? Whh_h : Whh_p;
    const float* Y   = which ? g_xh : g_xp;
    float* hout      = which ? g_ht : g_hs;
    unsigned* ctr = &g_ctr[which];
    int steps = which ? THY : TP;
    int tid = threadIdx.x, lane = tid & 31, w = tid >> 5;
    int d = dblk * 8 + w;

    for (int i4 = tid; i4 < 4096; i4 += 256) {
        int idx = i4 * 4;
        int r = idx >> 9, k = idx & 511;
        int dl = r >> 2, g = r & 3;
        *(float4*)&wsm[idx] =
            *(const float4*)&Whh[((size_t)(g * 512 + dblk * 8 + dl)) * 512 + k];
    }
    __syncthreads();

    float c0 = 0.f, c1 = 0.f;
    for (int t = 0; t < steps; t++) {
        ull acc[2][4];
        #pragma unroll
        for (int g = 0; g < 4; g++) {
            acc[0][g] = dpack(Y[((size_t)t * BB + lane) * G4 + g * 512 + d], 0.f);
            acc[1][g] = dpack(Y[((size_t)t * BB + lane + 32) * G4 + g * 512 + d], 0.f);
        }
        if (t > 0) {
            gbar(ctr, 64u * (unsigned)t);
            const float* hp = hout + (size_t)(t - 1) * BB * HIDN;
            for (int k0 = 0; k0 < HIDN; k0 += 64) {
                __syncthreads();
                ldtile(tile, hp, k0, tid);
                __syncthreads();
                #pragma unroll
                for (int kk = 0; kk < 64; kk += 4) {
                    float4 hA = *(const float4*)&tile[lane][kk];
                    float4 hB = *(const float4*)&tile[lane + 32][kk];
                    ull hA0 = *(ull*)&hA.x, hA1 = *(ull*)&hA.z;
                    ull hB0 = *(ull*)&hB.x, hB1 = *(ull*)&hB.z;
                    #pragma unroll
                    for (int g = 0; g < 4; g++) {
                        float4 wv = *(const float4*)&wsm[(w * 4 + g) * 512 + k0 + kk];
                        ull w0 = *(ull*)&wv.x, w1 = *(ull*)&wv.z;
                        dfma(acc[0][g], w0, hA0);
                        dfma(acc[0][g], w1, hA1);
                        dfma(acc[1][g], w0, hB0);
                        dfma(acc[1][g], w1, hB1);
                    }
                }
            }
        }
        float ig, fg, gg, og;
        ig = sigm(dred(acc[0][0])); fg = sigm(dred(acc[0][1]));
        gg = tanhm(dred(acc[0][2])); og = sigm(dred(acc[0][3]));
        c0 = fg * c0 + ig * gg;
        hout[((size_t)t * BB + lane) * HIDN + d] = og * tanhm(c0);
        ig = sigm(dred(acc[1][0])); fg = sigm(dred(acc[1][1]));
        gg = tanhm(dred(acc[1][2])); og = sigm(dred(acc[1][3]));
        c1 = fg * c1 + ig * gg;
        hout[((size_t)t * BB + lane + 32) * HIDN + d] = og * tanhm(c1);
    }
}

// ------------------------- persistent match loop (f32x2) -------------------
__global__ void match_pers(const float* __restrict__ Wih_m,
                           const float* __restrict__ Whh_m,
                           const float* __restrict__ Wm,
                           const float* __restrict__ w_e) {
    extern __shared__ float sm[];
    float* wcat = sm;                              // 16*1024
    float* wm_s = sm + 16 * 1024;                  // 4*512
    float (*tile)[68] = (float(*)[68])(wm_s + 4 * 512);
    float* su  = (float*)(tile + 64);              // 512
    float* swe = su + 512;                         // 512
    float* se  = swe + 512;                        // 96
    int cta = blockIdx.x;
    int tid = threadIdx.x, lane = tid & 31, w = tid >> 5;

    for (int i4 = tid; i4 < 4096; i4 += 256) {
        int idx = i4 * 4;
        int r = idx >> 10, k = idx & 1023;
        int dl = r >> 2, g = r & 3;
        int grow = g * 512 + cta * 4 + dl;
        float4 v = (k < 512)
            ? *(const float4*)&Wih_m[(size_t)grow * 1024 + k]
            : *(const float4*)&Whh_m[(size_t)grow * 512 + (k - 512)];
        *(float4*)&wcat[idx] = v;
    }
    for (int i4 = tid; i4 < 512; i4 += 256) {
        int idx = i4 * 4;
        int nl = idx >> 9, k = idx & 511;
        *(float4*)&wm_s[idx] = *(const float4*)&Wm[(size_t)(cta * 4 + nl) * 512 + k];
    }
    __syncthreads();

    int bB = (w >> 2) * 32 + lane;
    int dloc = w & 3;
    int d = cta * 4 + dloc;
    int nl = tid >> 6, bD = tid & 63;
    float c_m = 0.f;
    unsigned ph = 0;

    for (int k = 0; k < THY; k++) {
        // ---- A: attention for batch b = cta (CTAs 0..63) ----
        if (cta < BB) {
            int b = cta;
            float w0 = (k > 0) ? g_wmhm[((size_t)k * BB + b) * HIDN + tid] : 0.f;
            float w1 = (k > 0) ? g_wmhm[((size_t)k * BB + b) * HIDN + tid + 256] : 0.f;
            su[tid]       = g_wtht[((size_t)k * BB + b) * HIDN + tid] + w0;
            su[tid + 256] = g_wtht[((size_t)k * BB + b) * HIDN + tid + 256] + w1;
            swe[tid]       = w_e[tid];
            swe[tid + 256] = w_e[tid + 256];
            __syncthreads();
            for (int j = w; j < TP; j += 8) {
                const float* row = g_wshs + ((size_t)j * BB + b) * HIDN;
                float p = 0.f;
                #pragma unroll 4
                for (int h = lane; h < HIDN; h += 32)
                    p = fmaf(tanhm(row[h] + su[h]), swe[h], p);
                #pragma unroll
                for (int off = 16; off; off >>= 1)
                    p += __shfl_xor_sync(0xffffffffu, p, off);
                if (lane == 0) se[j] = p;
            }
            __syncthreads();
            if (w == 0) {
                float v0 = se[lane], v1 = se[lane + 32];
                float v2 = (lane == 0) ? se[64] : -1e30f;
                float mx = fmaxf(fmaxf(v0, v1), v2);
                #pragma unroll
                for (int off = 16; off; off >>= 1)
                    mx = fmaxf(mx, __shfl_xor_sync(0xffffffffu, mx, off));
                float e0 = __expf(v0 - mx), e1 = __expf(v1 - mx);
                float e2 = (lane == 0) ? __expf(v2 - mx) : 0.f;
                float s = e0 + e1 + e2;
                #pragma unroll
                for (int off = 16; off; off >>= 1)
                    s += __shfl_xor_sync(0xffffffffu, s, off);
                float inv = __fdividef(1.f, s);
                se[lane] = e0 * inv; se[lane + 32] = e1 * inv;
                if (lane == 0) se[64] = e2 * inv;
            }
            __syncthreads();
            float a0 = 0.f, a1 = 0.f;
            #pragma unroll 5
            for (int j = 0; j < TP; j++) {
                float al = se[j];
                const float* hr = g_hs + ((size_t)j * BB + b) * HIDN;
                a0 = fmaf(al, hr[tid], a0);
                a1 = fmaf(al, hr[tid + 256], a1);
            }
            g_ak[((size_t)k * BB + b) * HIDN + tid]       = a0;
            g_ak[((size_t)k * BB + b) * HIDN + tid + 256] = a1;
        }
        gbar(&g_ctr[2], 128u * (++ph));

        // ---- B: cell GEMM + gates (f32x2) ----
        ull acc[4];
        #pragma unroll
        for (int g = 0; g < 4; g++)
            acc[g] = dpack(g_xhm[((size_t)k * BB + bB) * G4 + g * 512 + d], 0.f);
        const float* a_in = g_ak + (size_t)k * BB * HIDN;
        const float* h_in = g_hm + (size_t)k * BB * HIDN;
        for (int k0 = 0; k0 < 1024; k0 += 64) {
            const float* src = (k0 < 512) ? (a_in + k0) : (h_in + k0 - 512);
            __syncthreads();
            ldtile(tile, src, 0, tid);
            __syncthreads();
            #pragma unroll
            for (int kk = 0; kk < 64; kk += 4) {
                float4 hv = *(const float4*)&tile[bB][kk];
                ull h0 = *(ull*)&hv.x, h1 = *(ull*)&hv.z;
                #pragma unroll
                for (int g = 0; g < 4; g++) {
                    float4 wv = *(const float4*)&wcat[(dloc * 4 + g) * 1024 + k0 + kk];
                    ull w0 = *(ull*)&wv.x, w1 = *(ull*)&wv.z;
                    dfma(acc[g], w0, h0);
                    dfma(acc[g], w1, h1);
                }
            }
        }
        {
            float ig = sigm(dred(acc[0])), fg = sigm(dred(acc[1]));
            float gg = tanhm(dred(acc[2])), og = sigm(dred(acc[3]));
            c_m = fg * c_m + ig * gg;
            g_hm[((size_t)(k + 1) * BB + bB) * HIDN + d] = og * tanhm(c_m);
        }
        gbar(&g_ctr[2], 128u * (++ph));

        // ---- D: wmhm[k+1] = Wm @ h_m (f32x2) ----
        {
            const float* hmk = g_hm + (size_t)(k + 1) * BB * HIDN;
            ull s2 = dpack(0.f, 0.f);
            for (int k0 = 0; k0 < HIDN; k0 += 64) {
                __syncthreads();
                ldtile(tile, hmk, k0, tid);
                __syncthreads();
                #pragma unroll
                for (int kk = 0; kk < 64; kk += 4) {
                    float4 hv = *(const float4*)&tile[bD][kk];
                    float4 wv = *(const float4*)&wm_s[nl * 512 + k0 + kk];
                    ull h0 = *(ull*)&hv.x, h1 = *(ull*)&hv.z;
                    ull w0 = *(ull*)&wv.x, w1 = *(ull*)&wv.z;
                    dfma(s2, w0, h0);
                    dfma(s2, w1, h1);
                }
            }
            g_wmhm[((size_t)(k + 1) * BB + bD) * HIDN + cta * 4 + nl] = dred(s2);
        }
        if (k < THY - 1) gbar(&g_ctr[2], 128u * (++ph));
    }
}

// ------------------------- final classifier --------------------------------
__global__ void fc_out(const float* __restrict__ fc_w,
                       const float* __restrict__ fc_b,
                       float* __restrict__ out) {
    int b = blockIdx.x;
    int lane = threadIdx.x & 31, c = threadIdx.x >> 5;
    const float* hm = g_hm + (size_t)THY * BB * HIDN + (size_t)b * HIDN;
    const float* wr = fc_w + (size_t)c * HIDN;
    float p = 0.f;
    #pragma unroll 4
    for (int h = lane; h < HIDN; h += 32) p = fmaf(hm[h], wr[h], p);
    #pragma unroll
    for (int off = 16; off; off >>= 1) p += __shfl_xor_sync(0xffffffffu, p, off);
    if (lane == 0) out[b * 3 + c] = p + fc_b[c];
}

// ---------------------------------------------------------------------------
extern "C" void kernel_launch(void* const* d_in, const int* in_sizes, int n_in,
                              void* d_out, int out_size) {
    const float* pair  = (const float*)d_in[0];
    const float* w_e   = (const float*)d_in[3];
    const float* Ws    = (const float*)d_in[4];
    const float* Wt    = (const float*)d_in[5];
    const float* Wm    = (const float*)d_in[6];
    const float* fc_w  = (const float*)d_in[7];
    const float* fc_b  = (const float*)d_in[8];
    const float* Wih_p = (const float*)d_in[9];
    const float* Whh_p = (const float*)d_in[10];
    const float* bih_p = (const float*)d_in[11];
    const float* bhh_p = (const float*)d_in[12];
    const float* Wih_h = (const float*)d_in[13];
    const float* Whh_h = (const float*)d_in[14];
    const float* bih_h = (const float*)d_in[15];
    const float* bhh_h = (const float*)d_in[16];
    const float* Wih_m = (const float*)d_in[17];
    const float* Whh_m = (const float*)d_in[18];
    const float* bih_m = (const float*)d_in[19];
    const float* bhh_m = (const float*)d_in[20];
    float* out = (float*)d_out;

    float *p_xp, *p_xh, *p_xhm, *p_hs, *p_ht, *p_wshs, *p_wtht;
    cudaGetSymbolAddress((void**)&p_xp,   g_xp);
    cudaGetSymbolAddress((void**)&p_xh,   g_xh);
    cudaGetSymbolAddress((void**)&p_xhm,  g_xhm);
    cudaGetSymbolAddress((void**)&p_hs,   g_hs);
    cudaGetSymbolAddress((void**)&p_ht,   g_ht);
    cudaGetSymbolAddress((void**)&p_wshs, g_wshs);
    cudaGetSymbolAddress((void**)&p_wtht, g_wtht);

    static int smem_set = 0;
    int lstm_smem  = (32 * 512 + 64 * 68) * 4;
    int match_smem = (16 * 1024 + 4 * 512 + 64 * 68 + 512 + 512 + 96) * 4;
    if (!smem_set) {
        cudaFuncSetAttribute(lstm_pers,
            cudaFuncAttributeMaxDynamicSharedMemorySize, lstm_smem);
        cudaFuncSetAttribute(match_pers,
            cudaFuncAttributeMaxDynamicSharedMemorySize, match_smem);
        smem_set = 1;
    }

    kinit<<<1, 32>>>();

    // input preactivations (biases folded)
    gemm_mma<<<dim3(G4 / 64, (TP * BB + 127) / 128), 256>>>(
        nullptr, 0, pair, 1, Wih_p, EMBD, 0, bih_p, bhh_p,
        p_xp, TP * BB, G4, EMBD);
    gemm_mma<<<dim3(G4 / 64, (THY * BB) / 128), 256>>>(
        nullptr, 0, pair, 2 + 64, Wih_h, EMBD, 0, bih_h, bhh_h,
        p_xh, THY * BB, G4, EMBD);

    // both LSTM recurrences in one persistent kernel
    lstm_pers<<<128, 256, lstm_smem>>>(Whh_p, Whh_h);

    // attention precomputes + hoisted match-cell input half
    gemm_mma<<<dim3(HIDN / 64, (TP * BB + 127) / 128), 256>>>(
        p_hs, HIDN, nullptr, 0, Ws, HIDN, 0, nullptr, nullptr,
        p_wshs, TP * BB, HIDN, HIDN);
    gemm_mma<<<dim3(HIDN / 64, (THY * BB) / 128), 256>>>(
        p_ht, HIDN, nullptr, 0, Wt, HIDN, 0, nullptr, nullptr,
        p_wtht, THY * BB, HIDN, HIDN);
    gemm_mma<<<dim3(G4 / 64, (THY * BB) / 128), 256>>>(
        p_ht, HIDN, nullptr, 0, Wih_m, 2 * HIDN, HIDN, bih_m, bhh_m,
        p_xhm, THY * BB, G4, HIDN);

    // full match loop in one persistent kernel
    match_pers<<<128, 256, match_smem>>>(Wih_m, Whh_m, Wm, w_e);

    fc_out<<<64, 96>>>(fc_w, fc_b, out);
}

// round 7
// speedup vs baseline: 1.9631x; 1.0284x over previous
#include <cuda_runtime.h>
#include <cuda_bf16.h>

// ---------------------------------------------------------------------------
// MatchLSTM: B=64, premise steps TP=65, hyp THY=64, EMB=768, HID=512
// Round 7: R5 design with A-tile staging bug fixed (full 32-col coverage).
// ---------------------------------------------------------------------------
#define BB    64
#define TP    65
#define THY   64
#define HIDN  512
#define G4    2048
#define EMBD  768
#define LL    130

#define MXP   (TP * BB)     // 4160
#define MXH   (THY * BB)    // 4096

typedef unsigned long long ull;

// ------------------------- device scratch (no allocs) ----------------------
__device__ float g_xp[TP * BB * G4];
__device__ float g_xh[THY * BB * G4];
__device__ float g_xhm[THY * BB * G4];
__device__ float g_hs[TP * BB * HIDN];
__device__ float g_ht[THY * BB * HIDN];
__device__ float g_wshs[TP * BB * HIDN];
__device__ float g_wtht[THY * BB * HIDN];
__device__ float g_ak[THY * BB * HIDN];
__device__ float g_hm[(THY + 1) * BB * HIDN];     // slot 0 never written = 0
__device__ float g_wmhm[(THY + 1) * BB * HIDN];
__device__ unsigned g_ctr[8];

// bf16 hi/lo split buffers
__device__ __nv_bfloat16 g_bxph[MXP * EMBD], g_bxpl[MXP * EMBD];
__device__ __nv_bfloat16 g_bxhh[MXH * EMBD], g_bxhl[MXH * EMBD];
__device__ __nv_bfloat16 g_wp_h[G4 * EMBD],  g_wp_l[G4 * EMBD];
__device__ __nv_bfloat16 g_wh_h[G4 * EMBD],  g_wh_l[G4 * EMBD];
__device__ __nv_bfloat16 g_ws_h[HIDN * HIDN], g_ws_l[HIDN * HIDN];
__device__ __nv_bfloat16 g_wt_h[HIDN * HIDN], g_wt_l[HIDN * HIDN];
__device__ __nv_bfloat16 g_wmr_h[G4 * HIDN],  g_wmr_l[G4 * HIDN];
__device__ __nv_bfloat16 g_hsbh[MXP * HIDN],  g_hsbl[MXP * HIDN];
__device__ __nv_bfloat16 g_htbh[MXH * HIDN],  g_htbl[MXH * HIDN];

// ------------------------- packed f32x2 FMA --------------------------------
__device__ __forceinline__ void dfma(ull& c, ull a, ull b) {
    asm("fma.rn.f32x2 %0, %1, %2, %0;" : "+l"(c) : "l"(a), "l"(b));
}
__device__ __forceinline__ float dred(ull c) {
    float2 f = *(float2*)&c;
    return f.x + f.y;
}
__device__ __forceinline__ ull dpack(float x, float y) {
    float2 f = make_float2(x, y);
    return *(ull*)&f;
}

// ------------------------- activations -------------------------------------
__device__ __forceinline__ float sigm(float x) {
    return __fdividef(1.f, 1.f + __expf(-x));
}
__device__ __forceinline__ float tanhm(float x) {
    return __fdividef(2.f, 1.f + __expf(-2.f * x)) - 1.f;
}

// ------------------------- grid-group barrier ------------------------------
__device__ __forceinline__ void gbar(unsigned* ctr, unsigned expected) {
    __threadfence();
    __syncthreads();
    if (threadIdx.x == 0) {
        atomicAdd(ctr, 1u);
        while (*(volatile unsigned*)ctr < expected) { __nanosleep(32); }
        __threadfence();
    }
    __syncthreads();
}

__global__ void kinit() {
    if (threadIdx.x < 8) g_ctr[threadIdx.x] = 0;
}

// ------------------------- bf16 split conversion ---------------------------
__device__ __forceinline__ void bsplit2(float x, float y, unsigned& h, unsigned& l) {
    __nv_bfloat16 hx = __float2bfloat16_rn(x);
    __nv_bfloat16 hy = __float2bfloat16_rn(y);
    __nv_bfloat16 lx = __float2bfloat16_rn(x - __bfloat162float(hx));
    __nv_bfloat16 ly = __float2bfloat16_rn(y - __bfloat162float(hy));
    __nv_bfloat162 hh(hx, hy), llv(lx, ly);
    h = *(unsigned*)&hh; l = *(unsigned*)&llv;
}

// generic matrix split: src [rows x (ld)], take cols off..off+K -> hi/lo [rows x K]
__global__ void conv_mat(const float* __restrict__ src, int ld, int off,
                         __nv_bfloat16* __restrict__ hi,
                         __nv_bfloat16* __restrict__ lo, int rows, int K) {
    int i = blockIdx.x * 256 + threadIdx.x;
    int kq = K >> 2;
    int total = rows * kq;
    if (i >= total) return;
    int row = i / kq;
    int c4 = (i - row * kq) * 4;
    float4 v = *(const float4*)(src + (size_t)row * ld + off + c4);
    unsigned h0, l0, h1, l1;
    bsplit2(v.x, v.y, h0, l0);
    bsplit2(v.z, v.w, h1, l1);
    *(uint2*)(hi + (size_t)row * K + c4) = make_uint2(h0, h1);
    *(uint2*)(lo + (size_t)row * K + c4) = make_uint2(l0, l1);
}

// gathered pair split: row m -> pair[b=m%64, l_off + m/64, :EMBD]
__global__ void conv_pair(const float* __restrict__ pair, int l_off,
                          __nv_bfloat16* __restrict__ hi,
                          __nv_bfloat16* __restrict__ lo, int rows) {
    int i = blockIdx.x * 256 + threadIdx.x;
    int kq = EMBD >> 2;
    int total = rows * kq;
    if (i >= total) return;
    int row = i / kq;
    int c4 = (i - row * kq) * 4;
    int t = row >> 6, b = row & 63;
    float4 v = *(const float4*)(pair + ((size_t)b * LL + l_off + t) * EMBD + c4);
    unsigned h0, l0, h1, l1;
    bsplit2(v.x, v.y, h0, l0);
    bsplit2(v.z, v.w, h1, l1);
    *(uint2*)(hi + (size_t)row * EMBD + c4) = make_uint2(h0, h1);
    *(uint2*)(lo + (size_t)row * EMBD + c4) = make_uint2(l0, l1);
}

// ------------------------- ldmatrix helper ---------------------------------
__device__ __forceinline__ void ldm_x4(unsigned r[4], const __nv_bfloat16* p) {
    unsigned a = (unsigned)__cvta_generic_to_shared(p);
    asm volatile("ldmatrix.sync.aligned.m8n8.x4.shared.b16 {%0,%1,%2,%3},[%4];"
                 : "=r"(r[0]), "=r"(r[1]), "=r"(r[2]), "=r"(r[3]) : "r"(a));
}

// ------------------------- bf16-split tensor GEMM --------------------------
// C[M,N] = (Ahi+Alo)[M,K] @ (Whi+Wlo)[N,K]^T + b1 + b2   (lo*lo dropped)
// BM=128, BN=64, BK=32, 256 threads, warps 4(m) x 2(n), warp tile 32x32.
__global__ void __launch_bounds__(256, 2)
gemm_bf16(const __nv_bfloat16* __restrict__ Ahi, const __nv_bfloat16* __restrict__ Alo,
          const __nv_bfloat16* __restrict__ Whi, const __nv_bfloat16* __restrict__ Wlo,
          const float* __restrict__ b1, const float* __restrict__ b2,
          float* __restrict__ C, int M, int N, int K) {
    __shared__ __align__(16) __nv_bfloat16 sAh[128][40], sAl[128][40];
    __shared__ __align__(16) __nv_bfloat16 sBh[64][40],  sBl[64][40];
    int tid = threadIdx.x, lane = tid & 31, wid = tid >> 5;
    int m0 = blockIdx.y * 128, n0 = blockIdx.x * 64;
    int wm = wid & 3, wn = wid >> 2;

    float acc[2][4][4];
    #pragma unroll
    for (int i = 0; i < 2; i++)
        #pragma unroll
        for (int j = 0; j < 4; j++)
            #pragma unroll
            for (int r = 0; r < 4; r++) acc[i][j][r] = 0.f;

    // staging: A row=tid>>1, 16-col half=(tid&1) -> two uint4 (16 bf16) each;
    //          B row=tid>>2, 8-col quarter=(tid&3) -> one uint4 (8 bf16).
    int ar = tid >> 1, ac = (tid & 1) * 16;
    int am = m0 + ar; if (am >= M) am = M - 1;
    const __nv_bfloat16* gah = Ahi + (size_t)am * K + ac;
    const __nv_bfloat16* gal = Alo + (size_t)am * K + ac;
    int br = tid >> 2, bc = (tid & 3) * 8;
    const __nv_bfloat16* gbh = Whi + (size_t)(n0 + br) * K + bc;
    const __nv_bfloat16* gbl = Wlo + (size_t)(n0 + br) * K + bc;

    // ldmatrix per-lane row/col offsets
    int aRow = (lane & 7) + ((lane >> 3) & 1) * 8;
    int aCol = (lane >> 4) * 8;
    int bRow = (lane & 7) + (lane >> 4) * 8;
    int bCol = ((lane >> 3) & 1) * 8;

    for (int k0 = 0; k0 < K; k0 += 32) {
        uint4 vah0 = *(const uint4*)(gah + k0);
        uint4 vah1 = *(const uint4*)(gah + k0 + 8);
        uint4 val0 = *(const uint4*)(gal + k0);
        uint4 val1 = *(const uint4*)(gal + k0 + 8);
        uint4 vbh  = *(const uint4*)(gbh + k0);
        uint4 vbl  = *(const uint4*)(gbl + k0);
        __syncthreads();
        *(uint4*)&sAh[ar][ac]     = vah0;
        *(uint4*)&sAh[ar][ac + 8] = vah1;
        *(uint4*)&sAl[ar][ac]     = val0;
        *(uint4*)&sAl[ar][ac + 8] = val1;
        *(uint4*)&sBh[br][bc] = vbh;
        *(uint4*)&sBl[br][bc] = vbl;
        __syncthreads();

        #pragma unroll
        for (int ks = 0; ks < 32; ks += 16) {
            unsigned ah[2][4], al[2][4], bh[4][2], bl[4][2];
            #pragma unroll
            for (int mt = 0; mt < 2; mt++) {
                int mb = wm * 32 + mt * 16;
                ldm_x4(ah[mt], &sAh[mb + aRow][ks + aCol]);
                ldm_x4(al[mt], &sAl[mb + aRow][ks + aCol]);
            }
            #pragma unroll
            for (int ntp = 0; ntp < 2; ntp++) {
                int nb = wn * 32 + ntp * 16;
                unsigned t[4];
                ldm_x4(t, &sBh[nb + bRow][ks + bCol]);
                bh[ntp*2][0] = t[0]; bh[ntp*2][1] = t[1];
                bh[ntp*2+1][0] = t[2]; bh[ntp*2+1][1] = t[3];
                ldm_x4(t, &sBl[nb + bRow][ks + bCol]);
                bl[ntp*2][0] = t[0]; bl[ntp*2][1] = t[1];
                bl[ntp*2+1][0] = t[2]; bl[ntp*2+1][1] = t[3];
            }
            #pragma unroll
            for (int mt = 0; mt < 2; mt++)
                #pragma unroll
                for (int nt = 0; nt < 4; nt++) {
                    float* d = acc[mt][nt];
                    asm("mma.sync.aligned.m16n8k16.row.col.f32.bf16.bf16.f32 "
                        "{%0,%1,%2,%3},{%4,%5,%6,%7},{%8,%9},{%0,%1,%2,%3};"
                        : "+f"(d[0]), "+f"(d[1]), "+f"(d[2]), "+f"(d[3])
                        : "r"(ah[mt][0]), "r"(ah[mt][1]), "r"(ah[mt][2]), "r"(ah[mt][3]),
                          "r"(bh[nt][0]), "r"(bh[nt][1]));
                    asm("mma.sync.aligned.m16n8k16.row.col.f32.bf16.bf16.f32 "
                        "{%0,%1,%2,%3},{%4,%5,%6,%7},{%8,%9},{%0,%1,%2,%3};"
                        : "+f"(d[0]), "+f"(d[1]), "+f"(d[2]), "+f"(d[3])
                        : "r"(ah[mt][0]), "r"(ah[mt][1]), "r"(ah[mt][2]), "r"(ah[mt][3]),
                          "r"(bl[nt][0]), "r"(bl[nt][1]));
                    asm("mma.sync.aligned.m16n8k16.row.col.f32.bf16.bf16.f32 "
                        "{%0,%1,%2,%3},{%4,%5,%6,%7},{%8,%9},{%0,%1,%2,%3};"
                        : "+f"(d[0]), "+f"(d[1]), "+f"(d[2]), "+f"(d[3])
                        : "r"(al[mt][0]), "r"(al[mt][1]), "r"(al[mt][2]), "r"(al[mt][3]),
                          "r"(bh[nt][0]), "r"(bh[nt][1]));
                }
        }
    }

    int fr = lane >> 2, fc = (lane & 3) * 2;
    #pragma unroll
    for (int mt = 0; mt < 2; mt++) {
        #pragma unroll
        for (int nt = 0; nt < 4; nt++) {
            int n = n0 + wn * 32 + nt * 8 + fc;
            float bb0 = 0.f, bb1 = 0.f;
            if (b1) { bb0 += b1[n]; bb1 += b1[n + 1]; }
            if (b2) { bb0 += b2[n]; bb1 += b2[n + 1]; }
            int m = m0 + wm * 32 + mt * 16 + fr;
            if (m < M) {
                C[(size_t)m * N + n]     = acc[mt][nt][0] + bb0;
                C[(size_t)m * N + n + 1] = acc[mt][nt][1] + bb1;
            }
            if (m + 8 < M) {
                C[(size_t)(m + 8) * N + n]     = acc[mt][nt][2] + bb0;
                C[(size_t)(m + 8) * N + n + 1] = acc[mt][nt][3] + bb1;
            }
        }
    }
}

// ------------------------- 64x64 tile stage (256 thr) ----------------------
__device__ __forceinline__ void ldtile(float (*tile)[68],
                                       const float* __restrict__ src,
                                       int k0, int tid) {
    int bl = tid >> 2, ks = (tid & 3) * 16;
    const float4* s = (const float4*)(src + (size_t)bl * HIDN + k0 + ks);
    float4 a = s[0], b = s[1], c = s[2], d = s[3];
    *(float4*)&tile[bl][ks]      = a;
    *(float4*)&tile[bl][ks + 4]  = b;
    *(float4*)&tile[bl][ks + 8]  = c;
    *(float4*)&tile[bl][ks + 12] = d;
}

// ------------------------- persistent dual LSTM (f32x2) --------------------
__global__ void lstm_pers(const float* __restrict__ Whh_p,
                          const float* __restrict__ Whh_h) {
    extern __shared__ float sm[];
    float* wsm = sm;                              // 32*512
    float (*tile)[68] = (float(*)[68])(sm + 32 * 512);
    int cta = blockIdx.x;
    int which = cta >> 6;
    int dblk = cta & 63;
    const float* Whh = which ? Whh_h : Whh_p;
    const float* Y   = which ? g_xh : g_xp;
    float* hout      = which ? g_ht : g_hs;
    unsigned* ctr = &g_ctr[which];
    int steps = which ? THY : TP;
    int tid = threadIdx.x, lane = tid & 31, w = tid >> 5;
    int d = dblk * 8 + w;

    for (int i4 = tid; i4 < 4096; i4 += 256) {
        int idx = i4 * 4;
        int r = idx >> 9, k = idx & 511;
        int dl = r >> 2, g = r & 3;
        *(float4*)&wsm[idx] =
            *(const float4*)&Whh[((size_t)(g * 512 + dblk * 8 + dl)) * 512 + k];
    }
    __syncthreads();

    float c0 = 0.f, c1 = 0.f;
    for (int t = 0; t < steps; t++) {
        ull acc[2][4];
        #pragma unroll
        for (int g = 0; g < 4; g++) {
            acc[0][g] = dpack(Y[((size_t)t * BB + lane) * G4 + g * 512 + d], 0.f);
            acc[1][g] = dpack(Y[((size_t)t * BB + lane + 32) * G4 + g * 512 + d], 0.f);
        }
        if (t > 0) {
            gbar(ctr, 64u * (unsigned)t);
            const float* hp = hout + (size_t)(t - 1) * BB * HIDN;
            for (int k0 = 0; k0 < HIDN; k0 += 64) {
                __syncthreads();
                ldtile(tile, hp, k0, tid);
                __syncthreads();
                #pragma unroll
                for (int kk = 0; kk < 64; kk += 4) {
                    float4 hA = *(const float4*)&tile[lane][kk];
                    float4 hB = *(const float4*)&tile[lane + 32][kk];
                    ull hA0 = *(ull*)&hA.x, hA1 = *(ull*)&hA.z;
                    ull hB0 = *(ull*)&hB.x, hB1 = *(ull*)&hB.z;
                    #pragma unroll
                    for (int g = 0; g < 4; g++) {
                        float4 wv = *(const float4*)&wsm[(w * 4 + g) * 512 + k0 + kk];
                        ull w0 = *(ull*)&wv.x, w1 = *(ull*)&wv.z;
                        dfma(acc[0][g], w0, hA0);
                        dfma(acc[0][g], w1, hA1);
                        dfma(acc[1][g], w0, hB0);
                        dfma(acc[1][g], w1, hB1);
                    }
                }
            }
        }
        float ig, fg, gg, og;
        ig = sigm(dred(acc[0][0])); fg = sigm(dred(acc[0][1]));
        gg = tanhm(dred(acc[0][2])); og = sigm(dred(acc[0][3]));
        c0 = fg * c0 + ig * gg;
        hout[((size_t)t * BB + lane) * HIDN + d] = og * tanhm(c0);
        ig = sigm(dred(acc[1][0])); fg = sigm(dred(acc[1][1]));
        gg = tanhm(dred(acc[1][2])); og = sigm(dred(acc[1][3]));
        c1 = fg * c1 + ig * gg;
        hout[((size_t)t * BB + lane + 32) * HIDN + d] = og * tanhm(c1);
    }
}

// ------------------------- persistent match loop (f32x2) -------------------
__global__ void match_pers(const float* __restrict__ Wih_m,
                           const float* __restrict__ Whh_m,
                           const float* __restrict__ Wm,
                           const float* __restrict__ w_e) {
    extern __shared__ float sm[];
    float* wcat = sm;                              // 16*1024
    float* wm_s = sm + 16 * 1024;                  // 4*512
    float (*tile)[68] = (float(*)[68])(wm_s + 4 * 512);
    float* su  = (float*)(tile + 64);              // 512
    float* swe = su + 512;                         // 512
    float* se  = swe + 512;                        // 96
    int cta = blockIdx.x;
    int tid = threadIdx.x, lane = tid & 31, w = tid >> 5;

    for (int i4 = tid; i4 < 4096; i4 += 256) {
        int idx = i4 * 4;
        int r = idx >> 10, k = idx & 1023;
        int dl = r >> 2, g = r & 3;
        int grow = g * 512 + cta * 4 + dl;
        float4 v = (k < 512)
            ? *(const float4*)&Wih_m[(size_t)grow * 1024 + k]
            : *(const float4*)&Whh_m[(size_t)grow * 512 + (k - 512)];
        *(float4*)&wcat[idx] = v;
    }
    for (int i4 = tid; i4 < 512; i4 += 256) {
        int idx = i4 * 4;
        int nl = idx >> 9, k = idx & 511;
        *(float4*)&wm_s[idx] = *(const float4*)&Wm[(size_t)(cta * 4 + nl) * 512 + k];
    }
    __syncthreads();

    int bB = (w >> 2) * 32 + lane;
    int dloc = w & 3;
    int d = cta * 4 + dloc;
    int nl = tid >> 6, bD = tid & 63;
    float c_m = 0.f;
    unsigned ph = 0;

    for (int k = 0; k < THY; k++) {
        // ---- A: attention for batch b = cta (CTAs 0..63) ----
        if (cta < BB) {
            int b = cta;
            float w0 = (k > 0) ? g_wmhm[((size_t)k * BB + b) * HIDN + tid] : 0.f;
            float w1 = (k > 0) ? g_wmhm[((size_t)k * BB + b) * HIDN + tid + 256] : 0.f;
            su[tid]       = g_wtht[((size_t)k * BB + b) * HIDN + tid] + w0;
            su[tid + 256] = g_wtht[((size_t)k * BB + b) * HIDN + tid + 256] + w1;
            swe[tid]       = w_e[tid];
            swe[tid + 256] = w_e[tid + 256];
            __syncthreads();
            for (int j = w; j < TP; j += 8) {
                const float* row = g_wshs + ((size_t)j * BB + b) * HIDN;
                float p = 0.f;
                #pragma unroll 4
                for (int h = lane; h < HIDN; h += 32)
                    p = fmaf(tanhm(row[h] + su[h]), swe[h], p);
                #pragma unroll
                for (int off = 16; off; off >>= 1)
                    p += __shfl_xor_sync(0xffffffffu, p, off);
                if (lane == 0) se[j] = p;
            }
            __syncthreads();
            if (w == 0) {
                float v0 = se[lane], v1 = se[lane + 32];
                float v2 = (lane == 0) ? se[64] : -1e30f;
                float mx = fmaxf(fmaxf(v0, v1), v2);
                #pragma unroll
                for (int off = 16; off; off >>= 1)
                    mx = fmaxf(mx, __shfl_xor_sync(0xffffffffu, mx, off));
                float e0 = __expf(v0 - mx), e1 = __expf(v1 - mx);
                float e2 = (lane == 0) ? __expf(v2 - mx) : 0.f;
                float s = e0 + e1 + e2;
                #pragma unroll
                for (int off = 16; off; off >>= 1)
                    s += __shfl_xor_sync(0xffffffffu, s, off);
                float inv = __fdividef(1.f, s);
                se[lane] = e0 * inv; se[lane + 32] = e1 * inv;
                if (lane == 0) se[64] = e2 * inv;
            }
            __syncthreads();
            float a0 = 0.f, a1 = 0.f;
            #pragma unroll 5
            for (int j = 0; j < TP; j++) {
                float al = se[j];
                const float* hr = g_hs + ((size_t)j * BB + b) * HIDN;
                a0 = fmaf(al, hr[tid], a0);
                a1 = fmaf(al, hr[tid + 256], a1);
            }
            g_ak[((size_t)k * BB + b) * HIDN + tid]       = a0;
            g_ak[((size_t)k * BB + b) * HIDN + tid + 256] = a1;
        }
        gbar(&g_ctr[2], 128u * (++ph));

        // ---- B: cell GEMM + gates (f32x2) ----
        ull acc[4];
        #pragma unroll
        for (int g = 0; g < 4; g++)
            acc[g] = dpack(g_xhm[((size_t)k * BB + bB) * G4 + g * 512 + d], 0.f);
        const float* a_in = g_ak + (size_t)k * BB * HIDN;
        const float* h_in = g_hm + (size_t)k * BB * HIDN;
        for (int k0 = 0; k0 < 1024; k0 += 64) {
            const float* src = (k0 < 512) ? (a_in + k0) : (h_in + k0 - 512);
            __syncthreads();
            ldtile(tile, src, 0, tid);
            __syncthreads();
            #pragma unroll
            for (int kk = 0; kk < 64; kk += 4) {
                float4 hv = *(const float4*)&tile[bB][kk];
                ull h0 = *(ull*)&hv.x, h1 = *(ull*)&hv.z;
                #pragma unroll
                for (int g = 0; g < 4; g++) {
                    float4 wv = *(const float4*)&wcat[(dloc * 4 + g) * 1024 + k0 + kk];
                    ull w0 = *(ull*)&wv.x, w1 = *(ull*)&wv.z;
                    dfma(acc[g], w0, h0);
                    dfma(acc[g], w1, h1);
                }
            }
        }
        {
            float ig = sigm(dred(acc[0])), fg = sigm(dred(acc[1]));
            float gg = tanhm(dred(acc[2])), og = sigm(dred(acc[3]));
            c_m = fg * c_m + ig * gg;
            g_hm[((size_t)(k + 1) * BB + bB) * HIDN + d] = og * tanhm(c_m);
        }
        gbar(&g_ctr[2], 128u * (++ph));

        // ---- D: wmhm[k+1] = Wm @ h_m (f32x2) ----
        {
            const float* hmk = g_hm + (size_t)(k + 1) * BB * HIDN;
            ull s2 = dpack(0.f, 0.f);
            for (int k0 = 0; k0 < HIDN; k0 += 64) {
                __syncthreads();
                ldtile(tile, hmk, k0, tid);
                __syncthreads();
                #pragma unroll
                for (int kk = 0; kk < 64; kk += 4) {
                    float4 hv = *(const float4*)&tile[bD][kk];
                    float4 wv = *(const float4*)&wm_s[nl * 512 + k0 + kk];
                    ull h0 = *(ull*)&hv.x, h1 = *(ull*)&hv.z;
                    ull w0 = *(ull*)&wv.x, w1 = *(ull*)&wv.z;
                    dfma(s2, w0, h0);
                    dfma(s2, w1, h1);
                }
            }
            g_wmhm[((size_t)(k + 1) * BB + bD) * HIDN + cta * 4 + nl] = dred(s2);
        }
        if (k < THY - 1) gbar(&g_ctr[2], 128u * (++ph));
    }
}

// ------------------------- final classifier --------------------------------
__global__ void fc_out(const float* __restrict__ fc_w,
                       const float* __restrict__ fc_b,
                       float* __restrict__ out) {
    int b = blockIdx.x;
    int lane = threadIdx.x & 31, c = threadIdx.x >> 5;
    const float* hm = g_hm + (size_t)THY * BB * HIDN + (size_t)b * HIDN;
    const float* wr = fc_w + (size_t)c * HIDN;
    float p = 0.f;
    #pragma unroll 4
    for (int h = lane; h < HIDN; h += 32) p = fmaf(hm[h], wr[h], p);
    #pragma unroll
    for (int off = 16; off; off >>= 1) p += __shfl_xor_sync(0xffffffffu, p, off);
    if (lane == 0) out[b * 3 + c] = p + fc_b[c];
}

// ---------------------------------------------------------------------------
extern "C" void kernel_launch(void* const* d_in, const int* in_sizes, int n_in,
                              void* d_out, int out_size) {
    const float* pair  = (const float*)d_in[0];
    const float* w_e   = (const float*)d_in[3];
    const float* Ws    = (const float*)d_in[4];
    const float* Wt    = (const float*)d_in[5];
    const float* Wm    = (const float*)d_in[6];
    const float* fc_w  = (const float*)d_in[7];
    const float* fc_b  = (const float*)d_in[8];
    const float* Wih_p = (const float*)d_in[9];
    const float* Whh_p = (const float*)d_in[10];
    const float* bih_p = (const float*)d_in[11];
    const float* bhh_p = (const float*)d_in[12];
    const float* Wih_h = (const float*)d_in[13];
    const float* Whh_h = (const float*)d_in[14];
    const float* bih_h = (const float*)d_in[15];
    const float* bhh_h = (const float*)d_in[16];
    const float* Wih_m = (const float*)d_in[17];
    const float* Whh_m = (const float*)d_in[18];
    const float* bih_m = (const float*)d_in[19];
    const float* bhh_m = (const float*)d_in[20];
    float* out = (float*)d_out;

    float *p_xp, *p_xh, *p_xhm, *p_hs, *p_ht, *p_wshs, *p_wtht;
    cudaGetSymbolAddress((void**)&p_xp,   g_xp);
    cudaGetSymbolAddress((void**)&p_xh,   g_xh);
    cudaGetSymbolAddress((void**)&p_xhm,  g_xhm);
    cudaGetSymbolAddress((void**)&p_hs,   g_hs);
    cudaGetSymbolAddress((void**)&p_ht,   g_ht);
    cudaGetSymbolAddress((void**)&p_wshs, g_wshs);
    cudaGetSymbolAddress((void**)&p_wtht, g_wtht);

    __nv_bfloat16 *bxph,*bxpl,*bxhh,*bxhl,*wph,*wpl,*whh,*whl;
    __nv_bfloat16 *wsh,*wsl,*wth,*wtl,*wmrh,*wmrl,*hsh,*hsl,*hth,*htl;
    cudaGetSymbolAddress((void**)&bxph, g_bxph);
    cudaGetSymbolAddress((void**)&bxpl, g_bxpl);
    cudaGetSymbolAddress((void**)&bxhh, g_bxhh);
    cudaGetSymbolAddress((void**)&bxhl, g_bxhl);
    cudaGetSymbolAddress((void**)&wph,  g_wp_h);
    cudaGetSymbolAddress((void**)&wpl,  g_wp_l);
    cudaGetSymbolAddress((void**)&whh,  g_wh_h);
    cudaGetSymbolAddress((void**)&whl,  g_wh_l);
    cudaGetSymbolAddress((void**)&wsh,  g_ws_h);
    cudaGetSymbolAddress((void**)&wsl,  g_ws_l);
    cudaGetSymbolAddress((void**)&wth,  g_wt_h);
    cudaGetSymbolAddress((void**)&wtl,  g_wt_l);
    cudaGetSymbolAddress((void**)&wmrh, g_wmr_h);
    cudaGetSymbolAddress((void**)&wmrl, g_wmr_l);
    cudaGetSymbolAddress((void**)&hsh,  g_hsbh);
    cudaGetSymbolAddress((void**)&hsl,  g_hsbl);
    cudaGetSymbolAddress((void**)&hth,  g_htbh);
    cudaGetSymbolAddress((void**)&htl,  g_htbl);

    static int smem_set = 0;
    int lstm_smem  = (32 * 512 + 64 * 68) * 4;
    int match_smem = (16 * 1024 + 4 * 512 + 64 * 68 + 512 + 512 + 96) * 4;
    if (!smem_set) {
        cudaFuncSetAttribute(lstm_pers,
            cudaFuncAttributeMaxDynamicSharedMemorySize, lstm_smem);
        cudaFuncSetAttribute(match_pers,
            cudaFuncAttributeMaxDynamicSharedMemorySize, match_smem);
        smem_set = 1;
    }

    kinit<<<1, 32>>>();

    // ---- conversions (inputs + weights) ----
    conv_pair<<<(MXP * (EMBD/4) + 255)/256, 256>>>(pair, 1,      bxph, bxpl, MXP);
    conv_pair<<<(MXH * (EMBD/4) + 255)/256, 256>>>(pair, 2 + 64, bxhh, bxhl, MXH);
    conv_mat<<<(G4 * (EMBD/4) + 255)/256, 256>>>(Wih_p, EMBD, 0, wph, wpl, G4, EMBD);
    conv_mat<<<(G4 * (EMBD/4) + 255)/256, 256>>>(Wih_h, EMBD, 0, whh, whl, G4, EMBD);
    conv_mat<<<(HIDN * (HIDN/4) + 255)/256, 256>>>(Ws, HIDN, 0, wsh, wsl, HIDN, HIDN);
    conv_mat<<<(HIDN * (HIDN/4) + 255)/256, 256>>>(Wt, HIDN, 0, wth, wtl, HIDN, HIDN);
    conv_mat<<<(G4 * (HIDN/4) + 255)/256, 256>>>(Wih_m, 2 * HIDN, HIDN, wmrh, wmrl, G4, HIDN);

    // ---- input preactivations ----
    gemm_bf16<<<dim3(G4/64, (MXP + 127)/128), 256>>>(
        bxph, bxpl, wph, wpl, bih_p, bhh_p, p_xp, MXP, G4, EMBD);
    gemm_bf16<<<dim3(G4/64, MXH/128), 256>>>(
        bxhh, bxhl, whh, whl, bih_h, bhh_h, p_xh, MXH, G4, EMBD);

    // ---- both LSTM recurrences ----
    lstm_pers<<<128, 256, lstm_smem>>>(Whh_p, Whh_h);

    // ---- convert h_s / h_t, then attention precomputes ----
    conv_mat<<<(MXP * (HIDN/4) + 255)/256, 256>>>(p_hs, HIDN, 0, hsh, hsl, MXP, HIDN);
    conv_mat<<<(MXH * (HIDN/4) + 255)/256, 256>>>(p_ht, HIDN, 0, hth, htl, MXH, HIDN);
    gemm_bf16<<<dim3(HIDN/64, (MXP + 127)/128), 256>>>(
        hsh, hsl, wsh, wsl, nullptr, nullptr, p_wshs, MXP, HIDN, HIDN);
    gemm_bf16<<<dim3(HIDN/64, MXH/128), 256>>>(
        hth, htl, wth, wtl, nullptr, nullptr, p_wtht, MXH, HIDN, HIDN);
    gemm_bf16<<<dim3(G4/64, MXH/128), 256>>>(
        hth, htl, wmrh, wmrl, bih_m, bhh_m, p_xhm, MXH, G4, HIDN);

    // ---- full match loop ----
    match_pers<<<128, 256, match_smem>>>(Wih_m, Whh_m, Wm, w_e);

    fc_out<<<64, 96>>>(fc_w, fc_b, out);
}

// round 10
// speedup vs baseline: 2.1291x; 1.0846x over previous
#include <cuda_runtime.h>
#include <cuda_bf16.h>
#include <cstdint>

// ---------------------------------------------------------------------------
// MatchLSTM: B=64, premise steps TP=65, hyp THY=64, EMB=768, HID=512
// Round 10: R7 (passing, 5472us) with fast release/acquire grid barriers
// (no membar.gl, no atomic round-trip, no nanosleep).
// ---------------------------------------------------------------------------
#define BB    64
#define TP    65
#define THY   64
#define HIDN  512
#define G4    2048
#define EMBD  768
#define LL    130

#define MXP   (TP * BB)     // 4160
#define MXH   (THY * BB)    // 4096

typedef unsigned long long ull;
typedef unsigned int u32;

// ------------------------- device scratch (no allocs) ----------------------
__device__ float g_xp[TP * BB * G4];
__device__ float g_xh[THY * BB * G4];
__device__ float g_xhm[THY * BB * G4];
__device__ float g_hs[TP * BB * HIDN];
__device__ float g_ht[THY * BB * HIDN];
__device__ float g_wshs[TP * BB * HIDN];
__device__ float g_wtht[THY * BB * HIDN];
__device__ float g_ak[THY * BB * HIDN];
__device__ float g_hm[(THY + 1) * BB * HIDN];     // slot 0 never written = 0
__device__ float g_wmhm[(THY + 1) * BB * HIDN];
__device__ unsigned g_ctr[8];

// bf16 hi/lo split buffers
__device__ __nv_bfloat16 g_bxph[MXP * EMBD], g_bxpl[MXP * EMBD];
__device__ __nv_bfloat16 g_bxhh[MXH * EMBD], g_bxhl[MXH * EMBD];
__device__ __nv_bfloat16 g_wp_h[G4 * EMBD],  g_wp_l[G4 * EMBD];
__device__ __nv_bfloat16 g_wh_h[G4 * EMBD],  g_wh_l[G4 * EMBD];
__device__ __nv_bfloat16 g_ws_h[HIDN * HIDN], g_ws_l[HIDN * HIDN];
__device__ __nv_bfloat16 g_wt_h[HIDN * HIDN], g_wt_l[HIDN * HIDN];
__device__ __nv_bfloat16 g_wmr_h[G4 * HIDN],  g_wmr_l[G4 * HIDN];
__device__ __nv_bfloat16 g_hsbh[MXP * HIDN],  g_hsbl[MXP * HIDN];
__device__ __nv_bfloat16 g_htbh[MXH * HIDN],  g_htbl[MXH * HIDN];

// ------------------------- packed f32x2 FMA --------------------------------
__device__ __forceinline__ void dfma(ull& c, ull a, ull b) {
    asm("fma.rn.f32x2 %0, %1, %2, %0;" : "+l"(c) : "l"(a), "l"(b));
}
__device__ __forceinline__ float dred(ull c) {
    float2 f = *(float2*)&c;
    return f.x + f.y;
}
__device__ __forceinline__ ull dpack(float x, float y) {
    float2 f = make_float2(x, y);
    return *(ull*)&f;
}

// ------------------------- activations -------------------------------------
__device__ __forceinline__ float sigm(float x) {
    return __fdividef(1.f, 1.f + __expf(-x));
}
__device__ __forceinline__ float tanhm(float x) {
    return __fdividef(2.f, 1.f + __expf(-2.f * x)) - 1.f;
}

// ------------------------- fast grid-group barrier -------------------------
// Arrival: release-RMW (publishes all prior writes, no membar, no return).
// Wait: tight acquire-load spin; syncthreads propagates ordering CTA-wide.
__device__ __forceinline__ void gbar(unsigned* ctr, unsigned expected) {
    __syncthreads();
    if (threadIdx.x == 0) {
        asm volatile("red.release.gpu.global.add.u32 [%0], %1;"
                     :: "l"(ctr), "r"(1u) : "memory");
        unsigned v;
        do {
            asm volatile("ld.acquire.gpu.global.u32 %0, [%1];"
                         : "=r"(v) : "l"(ctr) : "memory");
        } while (v < expected);
    }
    __syncthreads();
}

__global__ void kinit() {
    if (threadIdx.x < 8) g_ctr[threadIdx.x] = 0;
}

// ------------------------- bf16 split conversion ---------------------------
__device__ __forceinline__ void bsplit2(float x, float y, u32& h, u32& l) {
    __nv_bfloat16 hx = __float2bfloat16_rn(x);
    __nv_bfloat16 hy = __float2bfloat16_rn(y);
    __nv_bfloat16 lx = __float2bfloat16_rn(x - __bfloat162float(hx));
    __nv_bfloat16 ly = __float2bfloat16_rn(y - __bfloat162float(hy));
    __nv_bfloat162 hh(hx, hy), llv(lx, ly);
    h = *(u32*)&hh; l = *(u32*)&llv;
}

__global__ void conv_mat(const float* __restrict__ src, int ld, int off,
                         __nv_bfloat16* __restrict__ hi,
                         __nv_bfloat16* __restrict__ lo, int rows, int K) {
    int i = blockIdx.x * 256 + threadIdx.x;
    int kq = K >> 2;
    int total = rows * kq;
    if (i >= total) return;
    int row = i / kq;
    int c4 = (i - row * kq) * 4;
    float4 v = *(const float4*)(src + (size_t)row * ld + off + c4);
    u32 h0, l0, h1, l1;
    bsplit2(v.x, v.y, h0, l0);
    bsplit2(v.z, v.w, h1, l1);
    *(uint2*)(hi + (size_t)row * K + c4) = make_uint2(h0, h1);
    *(uint2*)(lo + (size_t)row * K + c4) = make_uint2(l0, l1);
}

__global__ void conv_pair(const float* __restrict__ pair, int l_off,
                          __nv_bfloat16* __restrict__ hi,
                          __nv_bfloat16* __restrict__ lo, int rows) {
    int i = blockIdx.x * 256 + threadIdx.x;
    int kq = EMBD >> 2;
    int total = rows * kq;
    if (i >= total) return;
    int row = i / kq;
    int c4 = (i - row * kq) * 4;
    int t = row >> 6, b = row & 63;
    float4 v = *(const float4*)(pair + ((size_t)b * LL + l_off + t) * EMBD + c4);
    u32 h0, l0, h1, l1;
    bsplit2(v.x, v.y, h0, l0);
    bsplit2(v.z, v.w, h1, l1);
    *(uint2*)(hi + (size_t)row * EMBD + c4) = make_uint2(h0, h1);
    *(uint2*)(lo + (size_t)row * EMBD + c4) = make_uint2(l0, l1);
}

// ------------------------- ldmatrix helper ---------------------------------
__device__ __forceinline__ void ldm_x4(u32 r[4], const __nv_bfloat16* p) {
    u32 a = (u32)__cvta_generic_to_shared(p);
    asm volatile("ldmatrix.sync.aligned.m8n8.x4.shared.b16 {%0,%1,%2,%3},[%4];"
                 : "=r"(r[0]), "=r"(r[1]), "=r"(r[2]), "=r"(r[3]) : "r"(a));
}

// ------------------------- bf16-split tensor GEMM --------------------------
// C[M,N] = (Ahi+Alo)[M,K] @ (Whi+Wlo)[N,K]^T + b1 + b2   (lo*lo dropped)
// BM=128, BN=64, BK=32, 256 threads, warps 4(m) x 2(n), warp tile 32x32.
__global__ void __launch_bounds__(256, 2)
gemm_bf16(const __nv_bfloat16* __restrict__ Ahi, const __nv_bfloat16* __restrict__ Alo,
          const __nv_bfloat16* __restrict__ Whi, const __nv_bfloat16* __restrict__ Wlo,
          const float* __restrict__ b1, const float* __restrict__ b2,
          float* __restrict__ C, int M, int N, int K) {
    __shared__ __align__(16) __nv_bfloat16 sAh[128][40], sAl[128][40];
    __shared__ __align__(16) __nv_bfloat16 sBh[64][40],  sBl[64][40];
    int tid = threadIdx.x, lane = tid & 31, wid = tid >> 5;
    int m0 = blockIdx.y * 128, n0 = blockIdx.x * 64;
    int wm = wid & 3, wn = wid >> 2;

    float acc[2][4][4];
    #pragma unroll
    for (int i = 0; i < 2; i++)
        #pragma unroll
        for (int j = 0; j < 4; j++)
            #pragma unroll
            for (int r = 0; r < 4; r++) acc[i][j][r] = 0.f;

    int ar = tid >> 1, ac = (tid & 1) * 16;
    int am = m0 + ar; if (am >= M) am = M - 1;
    const __nv_bfloat16* gah = Ahi + (size_t)am * K + ac;
    const __nv_bfloat16* gal = Alo + (size_t)am * K + ac;
    int br = tid >> 2, bc = (tid & 3) * 8;
    const __nv_bfloat16* gbh = Whi + (size_t)(n0 + br) * K + bc;
    const __nv_bfloat16* gbl = Wlo + (size_t)(n0 + br) * K + bc;

    int aRow = (lane & 7) + ((lane >> 3) & 1) * 8;
    int aCol = (lane >> 4) * 8;
    int bRow = (lane & 7) + (lane >> 4) * 8;
    int bCol = ((lane >> 3) & 1) * 8;

    for (int k0 = 0; k0 < K; k0 += 32) {
        uint4 vah0 = *(const uint4*)(gah + k0);
        uint4 vah1 = *(const uint4*)(gah + k0 + 8);
        uint4 val0 = *(const uint4*)(gal + k0);
        uint4 val1 = *(const uint4*)(gal + k0 + 8);
        uint4 vbh  = *(const uint4*)(gbh + k0);
        uint4 vbl  = *(const uint4*)(gbl + k0);
        __syncthreads();
        *(uint4*)&sAh[ar][ac]     = vah0;
        *(uint4*)&sAh[ar][ac + 8] = vah1;
        *(uint4*)&sAl[ar][ac]     = val0;
        *(uint4*)&sAl[ar][ac + 8] = val1;
        *(uint4*)&sBh[br][bc] = vbh;
        *(uint4*)&sBl[br][bc] = vbl;
        __syncthreads();

        #pragma unroll
        for (int ks = 0; ks < 32; ks += 16) {
            u32 ah[2][4], al[2][4], bh[4][2], bl[4][2];
            #pragma unroll
            for (int mt = 0; mt < 2; mt++) {
                int mb = wm * 32 + mt * 16;
                ldm_x4(ah[mt], &sAh[mb + aRow][ks + aCol]);
                ldm_x4(al[mt], &sAl[mb + aRow][ks + aCol]);
            }
            #pragma unroll
            for (int ntp = 0; ntp < 2; ntp++) {
                int nb = wn * 32 + ntp * 16;
                u32 t[4];
                ldm_x4(t, &sBh[nb + bRow][ks + bCol]);
                bh[ntp*2][0] = t[0]; bh[ntp*2][1] = t[1];
                bh[ntp*2+1][0] = t[2]; bh[ntp*2+1][1] = t[3];
                ldm_x4(t, &sBl[nb + bRow][ks + bCol]);
                bl[ntp*2][0] = t[0]; bl[ntp*2][1] = t[1];
                bl[ntp*2+1][0] = t[2]; bl[ntp*2+1][1] = t[3];
            }
            #pragma unroll
            for (int mt = 0; mt < 2; mt++)
                #pragma unroll
                for (int nt = 0; nt < 4; nt++) {
                    float* d = acc[mt][nt];
                    asm("mma.sync.aligned.m16n8k16.row.col.f32.bf16.bf16.f32 "
                        "{%0,%1,%2,%3},{%4,%5,%6,%7},{%8,%9},{%0,%1,%2,%3};"
                        : "+f"(d[0]), "+f"(d[1]), "+f"(d[2]), "+f"(d[3])
                        : "r"(ah[mt][0]), "r"(ah[mt][1]), "r"(ah[mt][2]), "r"(ah[mt][3]),
                          "r"(bh[nt][0]), "r"(bh[nt][1]));
                    asm("mma.sync.aligned.m16n8k16.row.col.f32.bf16.bf16.f32 "
                        "{%0,%1,%2,%3},{%4,%5,%6,%7},{%8,%9},{%0,%1,%2,%3};"
                        : "+f"(d[0]), "+f"(d[1]), "+f"(d[2]), "+f"(d[3])
                        : "r"(ah[mt][0]), "r"(ah[mt][1]), "r"(ah[mt][2]), "r"(ah[mt][3]),
                          "r"(bl[nt][0]), "r"(bl[nt][1]));
                    asm("mma.sync.aligned.m16n8k16.row.col.f32.bf16.bf16.f32 "
                        "{%0,%1,%2,%3},{%4,%5,%6,%7},{%8,%9},{%0,%1,%2,%3};"
                        : "+f"(d[0]), "+f"(d[1]), "+f"(d[2]), "+f"(d[3])
                        : "r"(al[mt][0]), "r"(al[mt][1]), "r"(al[mt][2]), "r"(al[mt][3]),
                          "r"(bh[nt][0]), "r"(bh[nt][1]));
                }
        }
    }

    int fr = lane >> 2, fc = (lane & 3) * 2;
    #pragma unroll
    for (int mt = 0; mt < 2; mt++) {
        #pragma unroll
        for (int nt = 0; nt < 4; nt++) {
            int n = n0 + wn * 32 + nt * 8 + fc;
            float bb0 = 0.f, bb1 = 0.f;
            if (b1) { bb0 += b1[n]; bb1 += b1[n + 1]; }
            if (b2) { bb0 += b2[n]; bb1 += b2[n + 1]; }
            int m = m0 + wm * 32 + mt * 16 + fr;
            if (m < M) {
                C[(size_t)m * N + n]     = acc[mt][nt][0] + bb0;
                C[(size_t)m * N + n + 1] = acc[mt][nt][1] + bb1;
            }
            if (m + 8 < M) {
                C[(size_t)(m + 8) * N + n]     = acc[mt][nt][2] + bb0;
                C[(size_t)(m + 8) * N + n + 1] = acc[mt][nt][3] + bb1;
            }
        }
    }
}

// ------------------------- 64x64 tile stage (256 thr) ----------------------
__device__ __forceinline__ void ldtile(float (*tile)[68],
                                       const float* __restrict__ src,
                                       int k0, int tid) {
    int bl = tid >> 2, ks = (tid & 3) * 16;
    const float4* s = (const float4*)(src + (size_t)bl * HIDN + k0 + ks);
    float4 a = s[0], b = s[1], c = s[2], d = s[3];
    *(float4*)&tile[bl][ks]      = a;
    *(float4*)&tile[bl][ks + 4]  = b;
    *(float4*)&tile[bl][ks + 8]  = c;
    *(float4*)&tile[bl][ks + 12] = d;
}

// ------------------------- persistent dual LSTM (f32x2) --------------------
__global__ void lstm_pers(const float* __restrict__ Whh_p,
                          const float* __restrict__ Whh_h) {
    extern __shared__ float sm[];
    float* wsm = sm;                              // 32*512
    float (*tile)[68] = (float(*)[68])(sm + 32 * 512);
    int cta = blockIdx.x;
    int which = cta >> 6;
    int dblk = cta & 63;
    const float* Whh = which ? Whh_h : Whh_p;
    const float* Y   = which ? g_xh : g_xp;
    float* hout      = which ? g_ht : g_hs;
    unsigned* ctr = &g_ctr[which];
    int steps = which ? THY : TP;
    int tid = threadIdx.x, lane = tid & 31, w = tid >> 5;
    int d = dblk * 8 + w;

    for (int i4 = tid; i4 < 4096; i4 += 256) {
        int idx = i4 * 4;
        int r = idx >> 9, k = idx & 511;
        int dl = r >> 2, g = r & 3;
        *(float4*)&wsm[idx] =
            *(const float4*)&Whh[((size_t)(g * 512 + dblk * 8 + dl)) * 512 + k];
    }
    __syncthreads();

    float c0 = 0.f, c1 = 0.f;
    for (int t = 0; t < steps; t++) {
        ull acc[2][4];
        #pragma unroll
        for (int g = 0; g < 4; g++) {
            acc[0][g] = dpack(Y[((size_t)t * BB + lane) * G4 + g * 512 + d], 0.f);
            acc[1][g] = dpack(Y[((size_t)t * BB + lane + 32) * G4 + g * 512 + d], 0.f);
        }
        if (t > 0) {
            gbar(ctr, 64u * (unsigned)t);
            const float* hp = hout + (size_t)(t - 1) * BB * HIDN;
            for (int k0 = 0; k0 < HIDN; k0 += 64) {
                __syncthreads();
                ldtile(tile, hp, k0, tid);
                __syncthreads();
                #pragma unroll
                for (int kk = 0; kk < 64; kk += 4) {
                    float4 hA = *(const float4*)&tile[lane][kk];
                    float4 hB = *(const float4*)&tile[lane + 32][kk];
                    ull hA0 = *(ull*)&hA.x, hA1 = *(ull*)&hA.z;
                    ull hB0 = *(ull*)&hB.x, hB1 = *(ull*)&hB.z;
                    #pragma unroll
                    for (int g = 0; g < 4; g++) {
                        float4 wv = *(const float4*)&wsm[(w * 4 + g) * 512 + k0 + kk];
                        ull w0 = *(ull*)&wv.x, w1 = *(ull*)&wv.z;
                        dfma(acc[0][g], w0, hA0);
                        dfma(acc[0][g], w1, hA1);
                        dfma(acc[1][g], w0, hB0);
                        dfma(acc[1][g], w1, hB1);
                    }
                }
            }
        }
        float ig, fg, gg, og;
        ig = sigm(dred(acc[0][0])); fg = sigm(dred(acc[0][1]));
        gg = tanhm(dred(acc[0][2])); og = sigm(dred(acc[0][3]));
        c0 = fg * c0 + ig * gg;
        hout[((size_t)t * BB + lane) * HIDN + d] = og * tanhm(c0);
        ig = sigm(dred(acc[1][0])); fg = sigm(dred(acc[1][1]));
        gg = tanhm(dred(acc[1][2])); og = sigm(dred(acc[1][3]));
        c1 = fg * c1 + ig * gg;
        hout[((size_t)t * BB + lane + 32) * HIDN + d] = og * tanhm(c1);
    }
}

// ------------------------- persistent match loop (f32x2) -------------------
__global__ void match_pers(const float* __restrict__ Wih_m,
                           const float* __restrict__ Whh_m,
                           const float* __restrict__ Wm,
                           const float* __restrict__ w_e) {
    extern __shared__ float sm[];
    float* wcat = sm;                              // 16*1024
    float* wm_s = sm + 16 * 1024;                  // 4*512
    float (*tile)[68] = (float(*)[68])(wm_s + 4 * 512);
    float* su  = (float*)(tile + 64);              // 512
    float* swe = su + 512;                         // 512
    float* se  = swe + 512;                        // 96
    int cta = blockIdx.x;
    int tid = threadIdx.x, lane = tid & 31, w = tid >> 5;

    for (int i4 = tid; i4 < 4096; i4 += 256) {
        int idx = i4 * 4;
        int r = idx >> 10, k = idx & 1023;
        int dl = r >> 2, g = r & 3;
        int grow = g * 512 + cta * 4 + dl;
        float4 v = (k < 512)
            ? *(const float4*)&Wih_m[(size_t)grow * 1024 + k]
            : *(const float4*)&Whh_m[(size_t)grow * 512 + (k - 512)];
        *(float4*)&wcat[idx] = v;
    }
    for (int i4 = tid; i4 < 512; i4 += 256) {
        int idx = i4 * 4;
        int nl = idx >> 9, k = idx & 511;
        *(float4*)&wm_s[idx] = *(const float4*)&Wm[(size_t)(cta * 4 + nl) * 512 + k];
    }
    __syncthreads();

    int bB = (w >> 2) * 32 + lane;
    int dloc = w & 3;
    int d = cta * 4 + dloc;
    int nl = tid >> 6, bD = tid & 63;
    float c_m = 0.f;
    unsigned ph = 0;

    for (int k = 0; k < THY; k++) {
        // ---- A: attention for batch b = cta (CTAs 0..63) ----
        if (cta < BB) {
            int b = cta;
            float w0 = (k > 0) ? g_wmhm[((size_t)k * BB + b) * HIDN + tid] : 0.f;
            float w1 = (k > 0) ? g_wmhm[((size_t)k * BB + b) * HIDN + tid + 256] : 0.f;
            su[tid]       = g_wtht[((size_t)k * BB + b) * HIDN + tid] + w0;
            su[tid + 256] = g_wtht[((size_t)k * BB + b) * HIDN + tid + 256] + w1;
            swe[tid]       = w_e[tid];
            swe[tid + 256] = w_e[tid + 256];
            __syncthreads();
            for (int j = w; j < TP; j += 8) {
                const float* row = g_wshs + ((size_t)j * BB + b) * HIDN;
                float p = 0.f;
                #pragma unroll 4
                for (int h = lane; h < HIDN; h += 32)
                    p = fmaf(tanhm(row[h] + su[h]), swe[h], p);
                #pragma unroll
                for (int off = 16; off; off >>= 1)
                    p += __shfl_xor_sync(0xffffffffu, p, off);
                if (lane == 0) se[j] = p;
            }
            __syncthreads();
            if (w == 0) {
                float v0 = se[lane], v1 = se[lane + 32];
                float v2 = (lane == 0) ? se[64] : -1e30f;
                float mx = fmaxf(fmaxf(v0, v1), v2);
                #pragma unroll
                for (int off = 16; off; off >>= 1)
                    mx = fmaxf(mx, __shfl_xor_sync(0xffffffffu, mx, off));
                float e0 = __expf(v0 - mx), e1 = __expf(v1 - mx);
                float e2 = (lane == 0) ? __expf(v2 - mx) : 0.f;
                float s = e0 + e1 + e2;
                #pragma unroll
                for (int off = 16; off; off >>= 1)
                    s += __shfl_xor_sync(0xffffffffu, s, off);
                float inv = __fdividef(1.f, s);
                se[lane] = e0 * inv; se[lane + 32] = e1 * inv;
                if (lane == 0) se[64] = e2 * inv;
            }
            __syncthreads();
            float a0 = 0.f, a1 = 0.f;
            #pragma unroll 5
            for (int j = 0; j < TP; j++) {
                float al = se[j];
                const float* hr = g_hs + ((size_t)j * BB + b) * HIDN;
                a0 = fmaf(al, hr[tid], a0);
                a1 = fmaf(al, hr[tid + 256], a1);
            }
            g_ak[((size_t)k * BB + b) * HIDN + tid]       = a0;
            g_ak[((size_t)k * BB + b) * HIDN + tid + 256] = a1;
        }
        gbar(&g_ctr[2], 128u * (++ph));

        // ---- B: cell GEMM + gates (f32x2) ----
        ull acc[4];
        #pragma unroll
        for (int g = 0; g < 4; g++)
            acc[g] = dpack(g_xhm[((size_t)k * BB + bB) * G4 + g * 512 + d], 0.f);
        const float* a_in = g_ak + (size_t)k * BB * HIDN;
        const float* h_in = g_hm + (size_t)k * BB * HIDN;
        for (int k0 = 0; k0 < 1024; k0 += 64) {
            const float* src = (k0 < 512) ? (a_in + k0) : (h_in + k0 - 512);
            __syncthreads();
            ldtile(tile, src, 0, tid);
            __syncthreads();
            #pragma unroll
            for (int kk = 0; kk < 64; kk += 4) {
                float4 hv = *(const float4*)&tile[bB][kk];
                ull h0 = *(ull*)&hv.x, h1 = *(ull*)&hv.z;
                #pragma unroll
                for (int g = 0; g < 4; g++) {
                    float4 wv = *(const float4*)&wcat[(dloc * 4 + g) * 1024 + k0 + kk];
                    ull w0 = *(ull*)&wv.x, w1 = *(ull*)&wv.z;
                    dfma(acc[g], w0, h0);
                    dfma(acc[g], w1, h1);
                }
            }
        }
        {
            float ig = sigm(dred(acc[0])), fg = sigm(dred(acc[1]));
            float gg = tanhm(dred(acc[2])), og = sigm(dred(acc[3]));
            c_m = fg * c_m + ig * gg;
            g_hm[((size_t)(k + 1) * BB + bB) * HIDN + d] = og * tanhm(c_m);
        }
        gbar(&g_ctr[2], 128u * (++ph));

        // ---- D: wmhm[k+1] = Wm @ h_m (f32x2) ----
        {
            const float* hmk = g_hm + (size_t)(k + 1) * BB * HIDN;
            ull s2 = dpack(0.f, 0.f);
            for (int k0 = 0; k0 < HIDN; k0 += 64) {
                __syncthreads();
                ldtile(tile, hmk, k0, tid);
                __syncthreads();
                #pragma unroll
                for (int kk = 0; kk < 64; kk += 4) {
                    float4 hv = *(const float4*)&tile[bD][kk];
                    float4 wv = *(const float4*)&wm_s[nl * 512 + k0 + kk];
                    ull h0 = *(ull*)&hv.x, h1 = *(ull*)&hv.z;
                    ull w0 = *(ull*)&wv.x, w1 = *(ull*)&wv.z;
                    dfma(s2, w0, h0);
                    dfma(s2, w1, h1);
                }
            }
            g_wmhm[((size_t)(k + 1) * BB + bD) * HIDN + cta * 4 + nl] = dred(s2);
        }
        if (k < THY - 1) gbar(&g_ctr[2], 128u * (++ph));
    }
}

// ------------------------- final classifier --------------------------------
__global__ void fc_out(const float* __restrict__ fc_w,
                       const float* __restrict__ fc_b,
                       float* __restrict__ out) {
    int b = blockIdx.x;
    int lane = threadIdx.x & 31, c = threadIdx.x >> 5;
    const float* hm = g_hm + (size_t)THY * BB * HIDN + (size_t)b * HIDN;
    const float* wr = fc_w + (size_t)c * HIDN;
    float p = 0.f;
    #pragma unroll 4
    for (int h = lane; h < HIDN; h += 32) p = fmaf(hm[h], wr[h], p);
    #pragma unroll
    for (int off = 16; off; off >>= 1) p += __shfl_xor_sync(0xffffffffu, p, off);
    if (lane == 0) out[b * 3 + c] = p + fc_b[c];
}

// ---------------------------------------------------------------------------
extern "C" void kernel_launch(void* const* d_in, const int* in_sizes, int n_in,
                              void* d_out, int out_size) {
    const float* pair  = (const float*)d_in[0];
    const float* w_e   = (const float*)d_in[3];
    const float* Ws    = (const float*)d_in[4];
    const float* Wt    = (const float*)d_in[5];
    const float* Wm    = (const float*)d_in[6];
    const float* fc_w  = (const float*)d_in[7];
    const float* fc_b  = (const float*)d_in[8];
    const float* Wih_p = (const float*)d_in[9];
    const float* Whh_p = (const float*)d_in[10];
    const float* bih_p = (const float*)d_in[11];
    const float* bhh_p = (const float*)d_in[12];
    const float* Wih_h = (const float*)d_in[13];
    const float* Whh_h = (const float*)d_in[14];
    const float* bih_h = (const float*)d_in[15];
    const float* bhh_h = (const float*)d_in[16];
    const float* Wih_m = (const float*)d_in[17];
    const float* Whh_m = (const float*)d_in[18];
    const float* bih_m = (const float*)d_in[19];
    const float* bhh_m = (const float*)d_in[20];
    float* out = (float*)d_out;

    float *p_xp, *p_xh, *p_xhm, *p_hs, *p_ht, *p_wshs, *p_wtht;
    cudaGetSymbolAddress((void**)&p_xp,   g_xp);
    cudaGetSymbolAddress((void**)&p_xh,   g_xh);
    cudaGetSymbolAddress((void**)&p_xhm,  g_xhm);
    cudaGetSymbolAddress((void**)&p_hs,   g_hs);
    cudaGetSymbolAddress((void**)&p_ht,   g_ht);
    cudaGetSymbolAddress((void**)&p_wshs, g_wshs);
    cudaGetSymbolAddress((void**)&p_wtht, g_wtht);

    __nv_bfloat16 *bxph,*bxpl,*bxhh,*bxhl,*wph,*wpl,*whh,*whl;
    __nv_bfloat16 *wsh,*wsl,*wth,*wtl,*wmrh,*wmrl,*hsh,*hsl,*hth,*htl;
    cudaGetSymbolAddress((void**)&bxph, g_bxph);
    cudaGetSymbolAddress((void**)&bxpl, g_bxpl);
    cudaGetSymbolAddress((void**)&bxhh, g_bxhh);
    cudaGetSymbolAddress((void**)&bxhl, g_bxhl);
    cudaGetSymbolAddress((void**)&wph,  g_wp_h);
    cudaGetSymbolAddress((void**)&wpl,  g_wp_l);
    cudaGetSymbolAddress((void**)&whh,  g_wh_h);
    cudaGetSymbolAddress((void**)&whl,  g_wh_l);
    cudaGetSymbolAddress((void**)&wsh,  g_ws_h);
    cudaGetSymbolAddress((void**)&wsl,  g_ws_l);
    cudaGetSymbolAddress((void**)&wth,  g_wt_h);
    cudaGetSymbolAddress((void**)&wtl,  g_wt_l);
    cudaGetSymbolAddress((void**)&wmrh, g_wmr_h);
    cudaGetSymbolAddress((void**)&wmrl, g_wmr_l);
    cudaGetSymbolAddress((void**)&hsh,  g_hsbh);
    cudaGetSymbolAddress((void**)&hsl,  g_hsbl);
    cudaGetSymbolAddress((void**)&hth,  g_htbh);
    cudaGetSymbolAddress((void**)&htl,  g_htbl);

    static int smem_set = 0;
    int lstm_smem  = (32 * 512 + 64 * 68) * 4;
    int match_smem = (16 * 1024 + 4 * 512 + 64 * 68 + 512 + 512 + 96) * 4;
    if (!smem_set) {
        cudaFuncSetAttribute(lstm_pers,
            cudaFuncAttributeMaxDynamicSharedMemorySize, lstm_smem);
        cudaFuncSetAttribute(match_pers,
            cudaFuncAttributeMaxDynamicSharedMemorySize, match_smem);
        smem_set = 1;
    }

    kinit<<<1, 32>>>();

    // ---- conversions (inputs + weights) ----
    conv_pair<<<(MXP * (EMBD/4) + 255)/256, 256>>>(pair, 1,      bxph, bxpl, MXP);
    conv_pair<<<(MXH * (EMBD/4) + 255)/256, 256>>>(pair, 2 + 64, bxhh, bxhl, MXH);
    conv_mat<<<(G4 * (EMBD/4) + 255)/256, 256>>>(Wih_p, EMBD, 0, wph, wpl, G4, EMBD);
    conv_mat<<<(G4 * (EMBD/4) + 255)/256, 256>>>(Wih_h, EMBD, 0, whh, whl, G4, EMBD);
    conv_mat<<<(HIDN * (HIDN/4) + 255)/256, 256>>>(Ws, HIDN, 0, wsh, wsl, HIDN, HIDN);
    conv_mat<<<(HIDN * (HIDN/4) + 255)/256, 256>>>(Wt, HIDN, 0, wth, wtl, HIDN, HIDN);
    conv_mat<<<(G4 * (HIDN/4) + 255)/256, 256>>>(Wih_m, 2 * HIDN, HIDN, wmrh, wmrl, G4, HIDN);

    // ---- input preactivations ----
    gemm_bf16<<<dim3(G4/64, (MXP + 127)/128), 256>>>(
        bxph, bxpl, wph, wpl, bih_p, bhh_p, p_xp, MXP, G4, EMBD);
    gemm_bf16<<<dim3(G4/64, MXH/128), 256>>>(
        bxhh, bxhl, whh, whl, bih_h, bhh_h, p_xh, MXH, G4, EMBD);

    // ---- both LSTM recurrences ----
    lstm_pers<<<128, 256, lstm_smem>>>(Whh_p, Whh_h);

    // ---- convert h_s / h_t, then attention precomputes ----
    conv_mat<<<(MXP * (HIDN/4) + 255)/256, 256>>>(p_hs, HIDN, 0, hsh, hsl, MXP, HIDN);
    conv_mat<<<(MXH * (HIDN/4) + 255)/256, 256>>>(p_ht, HIDN, 0, hth, htl, MXH, HIDN);
    gemm_bf16<<<dim3(HIDN/64, (MXP + 127)/128), 256>>>(
        hsh, hsl, wsh, wsl, nullptr, nullptr, p_wshs, MXP, HIDN, HIDN);
    gemm_bf16<<<dim3(HIDN/64, MXH/128), 256>>>(
        hth, htl, wth, wtl, nullptr, nullptr, p_wtht, MXH, HIDN, HIDN);
    gemm_bf16<<<dim3(G4/64, MXH/128), 256>>>(
        hth, htl, wmrh, wmrl, bih_m, bhh_m, p_xhm, MXH, G4, HIDN);

    // ---- full match loop ----
    match_pers<<<128, 256, match_smem>>>(Wih_m, Whh_m, Wm, w_e);

    fc_out<<<64, 96>>>(fc_w, fc_b, out);
}

// round 11
// speedup vs baseline: 2.3705x; 1.1134x over previous
#include <cuda_runtime.h>
#include <cuda_bf16.h>
#include <cstdint>

// ---------------------------------------------------------------------------
// MatchLSTM: B=64, premise steps TP=65, hyp THY=64, EMB=768, HID=512
// Round 11: R10 + software-pipelined tile loads (LSTM + match B/D phases),
// launch reorder so ncu (-s 5) profiles the big GEMM, w_e hoist.
// ---------------------------------------------------------------------------
#define BB    64
#define TP    65
#define THY   64
#define HIDN  512
#define G4    2048
#define EMBD  768
#define LL    130

#define MXP   (TP * BB)     // 4160
#define MXH   (THY * BB)    // 4096

typedef unsigned long long ull;
typedef unsigned int u32;

// ------------------------- device scratch (no allocs) ----------------------
__device__ float g_xp[TP * BB * G4];
__device__ float g_xh[THY * BB * G4];
__device__ float g_xhm[THY * BB * G4];
__device__ float g_hs[TP * BB * HIDN];
__device__ float g_ht[THY * BB * HIDN];
__device__ float g_wshs[TP * BB * HIDN];
__device__ float g_wtht[THY * BB * HIDN];
__device__ float g_ak[THY * BB * HIDN];
__device__ float g_hm[(THY + 1) * BB * HIDN];     // slot 0 never written = 0
__device__ float g_wmhm[(THY + 1) * BB * HIDN];
__device__ unsigned g_ctr[8];

// bf16 hi/lo split buffers
__device__ __nv_bfloat16 g_bxph[MXP * EMBD], g_bxpl[MXP * EMBD];
__device__ __nv_bfloat16 g_bxhh[MXH * EMBD], g_bxhl[MXH * EMBD];
__device__ __nv_bfloat16 g_wp_h[G4 * EMBD],  g_wp_l[G4 * EMBD];
__device__ __nv_bfloat16 g_wh_h[G4 * EMBD],  g_wh_l[G4 * EMBD];
__device__ __nv_bfloat16 g_ws_h[HIDN * HIDN], g_ws_l[HIDN * HIDN];
__device__ __nv_bfloat16 g_wt_h[HIDN * HIDN], g_wt_l[HIDN * HIDN];
__device__ __nv_bfloat16 g_wmr_h[G4 * HIDN],  g_wmr_l[G4 * HIDN];
__device__ __nv_bfloat16 g_hsbh[MXP * HIDN],  g_hsbl[MXP * HIDN];
__device__ __nv_bfloat16 g_htbh[MXH * HIDN],  g_htbl[MXH * HIDN];

// ------------------------- packed f32x2 FMA --------------------------------
__device__ __forceinline__ void dfma(ull& c, ull a, ull b) {
    asm("fma.rn.f32x2 %0, %1, %2, %0;" : "+l"(c) : "l"(a), "l"(b));
}
__device__ __forceinline__ float dred(ull c) {
    float2 f = *(float2*)&c;
    return f.x + f.y;
}
__device__ __forceinline__ ull dpack(float x, float y) {
    float2 f = make_float2(x, y);
    return *(ull*)&f;
}

// ------------------------- activations -------------------------------------
__device__ __forceinline__ float sigm(float x) {
    return __fdividef(1.f, 1.f + __expf(-x));
}
__device__ __forceinline__ float tanhm(float x) {
    return __fdividef(2.f, 1.f + __expf(-2.f * x)) - 1.f;
}

// ------------------------- fast grid-group barrier -------------------------
__device__ __forceinline__ void gbar(unsigned* ctr, unsigned expected) {
    __syncthreads();
    if (threadIdx.x == 0) {
        asm volatile("red.release.gpu.global.add.u32 [%0], %1;"
                     :: "l"(ctr), "r"(1u) : "memory");
        unsigned v;
        do {
            asm volatile("ld.acquire.gpu.global.u32 %0, [%1];"
                         : "=r"(v) : "l"(ctr) : "memory");
        } while (v < expected);
    }
    __syncthreads();
}

__global__ void kinit() {
    if (threadIdx.x < 8) g_ctr[threadIdx.x] = 0;
}

// ------------------------- bf16 split conversion ---------------------------
__device__ __forceinline__ void bsplit2(float x, float y, u32& h, u32& l) {
    __nv_bfloat16 hx = __float2bfloat16_rn(x);
    __nv_bfloat16 hy = __float2bfloat16_rn(y);
    __nv_bfloat16 lx = __float2bfloat16_rn(x - __bfloat162float(hx));
    __nv_bfloat16 ly = __float2bfloat16_rn(y - __bfloat162float(hy));
    __nv_bfloat162 hh(hx, hy), llv(lx, ly);
    h = *(u32*)&hh; l = *(u32*)&llv;
}

__global__ void conv_mat(const float* __restrict__ src, int ld, int off,
                         __nv_bfloat16* __restrict__ hi,
                         __nv_bfloat16* __restrict__ lo, int rows, int K) {
    int i = blockIdx.x * 256 + threadIdx.x;
    int kq = K >> 2;
    int total = rows * kq;
    if (i >= total) return;
    int row = i / kq;
    int c4 = (i - row * kq) * 4;
    float4 v = *(const float4*)(src + (size_t)row * ld + off + c4);
    u32 h0, l0, h1, l1;
    bsplit2(v.x, v.y, h0, l0);
    bsplit2(v.z, v.w, h1, l1);
    *(uint2*)(hi + (size_t)row * K + c4) = make_uint2(h0, h1);
    *(uint2*)(lo + (size_t)row * K + c4) = make_uint2(l0, l1);
}

__global__ void conv_pair(const float* __restrict__ pair, int l_off,
                          __nv_bfloat16* __restrict__ hi,
                          __nv_bfloat16* __restrict__ lo, int rows) {
    int i = blockIdx.x * 256 + threadIdx.x;
    int kq = EMBD >> 2;
    int total = rows * kq;
    if (i >= total) return;
    int row = i / kq;
    int c4 = (i - row * kq) * 4;
    int t = row >> 6, b = row & 63;
    float4 v = *(const float4*)(pair + ((size_t)b * LL + l_off + t) * EMBD + c4);
    u32 h0, l0, h1, l1;
    bsplit2(v.x, v.y, h0, l0);
    bsplit2(v.z, v.w, h1, l1);
    *(uint2*)(hi + (size_t)row * EMBD + c4) = make_uint2(h0, h1);
    *(uint2*)(lo + (size_t)row * EMBD + c4) = make_uint2(l0, l1);
}

// ------------------------- ldmatrix helper ---------------------------------
__device__ __forceinline__ void ldm_x4(u32 r[4], const __nv_bfloat16* p) {
    u32 a = (u32)__cvta_generic_to_shared(p);
    asm volatile("ldmatrix.sync.aligned.m8n8.x4.shared.b16 {%0,%1,%2,%3},[%4];"
                 : "=r"(r[0]), "=r"(r[1]), "=r"(r[2]), "=r"(r[3]) : "r"(a));
}

// ------------------------- bf16-split tensor GEMM --------------------------
__global__ void __launch_bounds__(256, 2)
gemm_bf16(const __nv_bfloat16* __restrict__ Ahi, const __nv_bfloat16* __restrict__ Alo,
          const __nv_bfloat16* __restrict__ Whi, const __nv_bfloat16* __restrict__ Wlo,
          const float* __restrict__ b1, const float* __restrict__ b2,
          float* __restrict__ C, int M, int N, int K) {
    __shared__ __align__(16) __nv_bfloat16 sAh[128][40], sAl[128][40];
    __shared__ __align__(16) __nv_bfloat16 sBh[64][40],  sBl[64][40];
    int tid = threadIdx.x, lane = tid & 31, wid = tid >> 5;
    int m0 = blockIdx.y * 128, n0 = blockIdx.x * 64;
    int wm = wid & 3, wn = wid >> 2;

    float acc[2][4][4];
    #pragma unroll
    for (int i = 0; i < 2; i++)
        #pragma unroll
        for (int j = 0; j < 4; j++)
            #pragma unroll
            for (int r = 0; r < 4; r++) acc[i][j][r] = 0.f;

    int ar = tid >> 1, ac = (tid & 1) * 16;
    int am = m0 + ar; if (am >= M) am = M - 1;
    const __nv_bfloat16* gah = Ahi + (size_t)am * K + ac;
    const __nv_bfloat16* gal = Alo + (size_t)am * K + ac;
    int br = tid >> 2, bc = (tid & 3) * 8;
    const __nv_bfloat16* gbh = Whi + (size_t)(n0 + br) * K + bc;
    const __nv_bfloat16* gbl = Wlo + (size_t)(n0 + br) * K + bc;

    int aRow = (lane & 7) + ((lane >> 3) & 1) * 8;
    int aCol = (lane >> 4) * 8;
    int bRow = (lane & 7) + (lane >> 4) * 8;
    int bCol = ((lane >> 3) & 1) * 8;

    for (int k0 = 0; k0 < K; k0 += 32) {
        uint4 vah0 = *(const uint4*)(gah + k0);
        uint4 vah1 = *(const uint4*)(gah + k0 + 8);
        uint4 val0 = *(const uint4*)(gal + k0);
        uint4 val1 = *(const uint4*)(gal + k0 + 8);
        uint4 vbh  = *(const uint4*)(gbh + k0);
        uint4 vbl  = *(const uint4*)(gbl + k0);
        __syncthreads();
        *(uint4*)&sAh[ar][ac]     = vah0;
        *(uint4*)&sAh[ar][ac + 8] = vah1;
        *(uint4*)&sAl[ar][ac]     = val0;
        *(uint4*)&sAl[ar][ac + 8] = val1;
        *(uint4*)&sBh[br][bc] = vbh;
        *(uint4*)&sBl[br][bc] = vbl;
        __syncthreads();

        #pragma unroll
        for (int ks = 0; ks < 32; ks += 16) {
            u32 ah[2][4], al[2][4], bh[4][2], bl[4][2];
            #pragma unroll
            for (int mt = 0; mt < 2; mt++) {
                int mb = wm * 32 + mt * 16;
                ldm_x4(ah[mt], &sAh[mb + aRow][ks + aCol]);
                ldm_x4(al[mt], &sAl[mb + aRow][ks + aCol]);
            }
            #pragma unroll
            for (int ntp = 0; ntp < 2; ntp++) {
                int nb = wn * 32 + ntp * 16;
                u32 t[4];
                ldm_x4(t, &sBh[nb + bRow][ks + bCol]);
                bh[ntp*2][0] = t[0]; bh[ntp*2][1] = t[1];
                bh[ntp*2+1][0] = t[2]; bh[ntp*2+1][1] = t[3];
                ldm_x4(t, &sBl[nb + bRow][ks + bCol]);
                bl[ntp*2][0] = t[0]; bl[ntp*2][1] = t[1];
                bl[ntp*2+1][0] = t[2]; bl[ntp*2+1][1] = t[3];
            }
            #pragma unroll
            for (int mt = 0; mt < 2; mt++)
                #pragma unroll
                for (int nt = 0; nt < 4; nt++) {
                    float* d = acc[mt][nt];
                    asm("mma.sync.aligned.m16n8k16.row.col.f32.bf16.bf16.f32 "
                        "{%0,%1,%2,%3},{%4,%5,%6,%7},{%8,%9},{%0,%1,%2,%3};"
                        : "+f"(d[0]), "+f"(d[1]), "+f"(d[2]), "+f"(d[3])
                        : "r"(ah[mt][0]), "r"(ah[mt][1]), "r"(ah[mt][2]), "r"(ah[mt][3]),
                          "r"(bh[nt][0]), "r"(bh[nt][1]));
                    asm("mma.sync.aligned.m16n8k16.row.col.f32.bf16.bf16.f32 "
                        "{%0,%1,%2,%3},{%4,%5,%6,%7},{%8,%9},{%0,%1,%2,%3};"
                        : "+f"(d[0]), "+f"(d[1]), "+f"(d[2]), "+f"(d[3])
                        : "r"(ah[mt][0]), "r"(ah[mt][1]), "r"(ah[mt][2]), "r"(ah[mt][3]),
                          "r"(bl[nt][0]), "r"(bl[nt][1]));
                    asm("mma.sync.aligned.m16n8k16.row.col.f32.bf16.bf16.f32 "
                        "{%0,%1,%2,%3},{%4,%5,%6,%7},{%8,%9},{%0,%1,%2,%3};"
                        : "+f"(d[0]), "+f"(d[1]), "+f"(d[2]), "+f"(d[3])
                        : "r"(al[mt][0]), "r"(al[mt][1]), "r"(al[mt][2]), "r"(al[mt][3]),
                          "r"(bh[nt][0]), "r"(bh[nt][1]));
                }
        }
    }

    int fr = lane >> 2, fc = (lane & 3) * 2;
    #pragma unroll
    for (int mt = 0; mt < 2; mt++) {
        #pragma unroll
        for (int nt = 0; nt < 4; nt++) {
            int n = n0 + wn * 32 + nt * 8 + fc;
            float bb0 = 0.f, bb1 = 0.f;
            if (b1) { bb0 += b1[n]; bb1 += b1[n + 1]; }
            if (b2) { bb0 += b2[n]; bb1 += b2[n + 1]; }
            int m = m0 + wm * 32 + mt * 16 + fr;
            if (m < M) {
                C[(size_t)m * N + n]     = acc[mt][nt][0] + bb0;
                C[(size_t)m * N + n + 1] = acc[mt][nt][1] + bb1;
            }
            if (m + 8 < M) {
                C[(size_t)(m + 8) * N + n]     = acc[mt][nt][2] + bb0;
                C[(size_t)(m + 8) * N + n + 1] = acc[mt][nt][3] + bb1;
            }
        }
    }
}

// ------------------------- pipelined tile helpers --------------------------
// load chunk into registers (4x float4 per thread)
__device__ __forceinline__ void ldregs(float4 r[4], const float* __restrict__ src,
                                       int bl, int ksl) {
    const float4* s = (const float4*)(src + (size_t)bl * HIDN + ksl);
    r[0] = s[0]; r[1] = s[1]; r[2] = s[2]; r[3] = s[3];
}
__device__ __forceinline__ void stregs(float (*tile)[68], const float4 r[4],
                                       int bl, int ksl) {
    *(float4*)&tile[bl][ksl]      = r[0];
    *(float4*)&tile[bl][ksl + 4]  = r[1];
    *(float4*)&tile[bl][ksl + 8]  = r[2];
    *(float4*)&tile[bl][ksl + 12] = r[3];
}

// ------------------------- persistent dual LSTM (f32x2, pipelined) ---------
__global__ void lstm_pers(const float* __restrict__ Whh_p,
                          const float* __restrict__ Whh_h) {
    extern __shared__ float sm[];
    float* wsm = sm;                              // 32*512
    float (*tile)[68] = (float(*)[68])(sm + 32 * 512);
    int cta = blockIdx.x;
    int which = cta >> 6;
    int dblk = cta & 63;
    const float* Whh = which ? Whh_h : Whh_p;
    const float* Y   = which ? g_xh : g_xp;
    float* hout      = which ? g_ht : g_hs;
    unsigned* ctr = &g_ctr[which];
    int steps = which ? THY : TP;
    int tid = threadIdx.x, lane = tid & 31, w = tid >> 5;
    int d = dblk * 8 + w;
    int bl = tid >> 2, ksl = (tid & 3) * 16;

    for (int i4 = tid; i4 < 4096; i4 += 256) {
        int idx = i4 * 4;
        int r = idx >> 9, k = idx & 511;
        int dl = r >> 2, g = r & 3;
        *(float4*)&wsm[idx] =
            *(const float4*)&Whh[((size_t)(g * 512 + dblk * 8 + dl)) * 512 + k];
    }
    __syncthreads();

    float c0 = 0.f, c1 = 0.f;
    for (int t = 0; t < steps; t++) {
        ull acc[2][4];
        #pragma unroll
        for (int g = 0; g < 4; g++) {
            acc[0][g] = dpack(Y[((size_t)t * BB + lane) * G4 + g * 512 + d], 0.f);
            acc[1][g] = dpack(Y[((size_t)t * BB + lane + 32) * G4 + g * 512 + d], 0.f);
        }
        if (t > 0) {
            gbar(ctr, 64u * (unsigned)t);
            const float* hp = hout + (size_t)(t - 1) * BB * HIDN;
            float4 rr[4];
            ldregs(rr, hp, bl, ksl);
            for (int k0 = 0; k0 < HIDN; k0 += 64) {
                __syncthreads();
                stregs(tile, rr, bl, ksl);
                __syncthreads();
                if (k0 + 64 < HIDN) ldregs(rr, hp + k0 + 64, bl, ksl);
                #pragma unroll
                for (int kk = 0; kk < 64; kk += 4) {
                    float4 hA = *(const float4*)&tile[lane][kk];
                    float4 hB = *(const float4*)&tile[lane + 32][kk];
                    ull hA0 = *(ull*)&hA.x, hA1 = *(ull*)&hA.z;
                    ull hB0 = *(ull*)&hB.x, hB1 = *(ull*)&hB.z;
                    #pragma unroll
                    for (int g = 0; g < 4; g++) {
                        float4 wv = *(const float4*)&wsm[(w * 4 + g) * 512 + k0 + kk];
                        ull w0 = *(ull*)&wv.x, w1 = *(ull*)&wv.z;
                        dfma(acc[0][g], w0, hA0);
                        dfma(acc[0][g], w1, hA1);
                        dfma(acc[1][g], w0, hB0);
                        dfma(acc[1][g], w1, hB1);
                    }
                }
            }
        }
        float ig, fg, gg, og;
        ig = sigm(dred(acc[0][0])); fg = sigm(dred(acc[0][1]));
        gg = tanhm(dred(acc[0][2])); og = sigm(dred(acc[0][3]));
        c0 = fg * c0 + ig * gg;
        hout[((size_t)t * BB + lane) * HIDN + d] = og * tanhm(c0);
        ig = sigm(dred(acc[1][0])); fg = sigm(dred(acc[1][1]));
        gg = tanhm(dred(acc[1][2])); og = sigm(dred(acc[1][3]));
        c1 = fg * c1 + ig * gg;
        hout[((size_t)t * BB + lane + 32) * HIDN + d] = og * tanhm(c1);
    }
}

// ------------------------- persistent match loop (f32x2, pipelined) --------
__global__ void match_pers(const float* __restrict__ Wih_m,
                           const float* __restrict__ Whh_m,
                           const float* __restrict__ Wm,
                           const float* __restrict__ w_e) {
    extern __shared__ float sm[];
    float* wcat = sm;                              // 16*1024
    float* wm_s = sm + 16 * 1024;                  // 4*512
    float (*tile)[68] = (float(*)[68])(wm_s + 4 * 512);
    float* su  = (float*)(tile + 64);              // 512
    float* swe = su + 512;                         // 512
    float* se  = swe + 512;                        // 96
    int cta = blockIdx.x;
    int tid = threadIdx.x, lane = tid & 31, w = tid >> 5;
    int bl = tid >> 2, ksl = (tid & 3) * 16;

    for (int i4 = tid; i4 < 4096; i4 += 256) {
        int idx = i4 * 4;
        int r = idx >> 10, k = idx & 1023;
        int dl = r >> 2, g = r & 3;
        int grow = g * 512 + cta * 4 + dl;
        float4 v = (k < 512)
            ? *(const float4*)&Wih_m[(size_t)grow * 1024 + k]
            : *(const float4*)&Whh_m[(size_t)grow * 512 + (k - 512)];
        *(float4*)&wcat[idx] = v;
    }
    for (int i4 = tid; i4 < 512; i4 += 256) {
        int idx = i4 * 4;
        int nl = idx >> 9, k = idx & 511;
        *(float4*)&wm_s[idx] = *(const float4*)&Wm[(size_t)(cta * 4 + nl) * 512 + k];
    }
    if (cta < BB) {                 // w_e hoisted out of the step loop
        swe[tid]       = w_e[tid];
        swe[tid + 256] = w_e[tid + 256];
    }
    __syncthreads();

    int bB = (w >> 2) * 32 + lane;
    int dloc = w & 3;
    int d = cta * 4 + dloc;
    int nl = tid >> 6, bD = tid & 63;
    float c_m = 0.f;
    unsigned ph = 0;

    for (int k = 0; k < THY; k++) {
        // ---- A: attention for batch b = cta (CTAs 0..63) ----
        if (cta < BB) {
            int b = cta;
            float w0 = (k > 0) ? g_wmhm[((size_t)k * BB + b) * HIDN + tid] : 0.f;
            float w1 = (k > 0) ? g_wmhm[((size_t)k * BB + b) * HIDN + tid + 256] : 0.f;
            su[tid]       = g_wtht[((size_t)k * BB + b) * HIDN + tid] + w0;
            su[tid + 256] = g_wtht[((size_t)k * BB + b) * HIDN + tid + 256] + w1;
            __syncthreads();
            for (int j = w; j < TP; j += 8) {
                const float* row = g_wshs + ((size_t)j * BB + b) * HIDN;
                float p = 0.f;
                #pragma unroll 4
                for (int h = lane; h < HIDN; h += 32)
                    p = fmaf(tanhm(row[h] + su[h]), swe[h], p);
                #pragma unroll
                for (int off = 16; off; off >>= 1)
                    p += __shfl_xor_sync(0xffffffffu, p, off);
                if (lane == 0) se[j] = p;
            }
            __syncthreads();
            if (w == 0) {
                float v0 = se[lane], v1 = se[lane + 32];
                float v2 = (lane == 0) ? se[64] : -1e30f;
                float mx = fmaxf(fmaxf(v0, v1), v2);
                #pragma unroll
                for (int off = 16; off; off >>= 1)
                    mx = fmaxf(mx, __shfl_xor_sync(0xffffffffu, mx, off));
                float e0 = __expf(v0 - mx), e1 = __expf(v1 - mx);
                float e2 = (lane == 0) ? __expf(v2 - mx) : 0.f;
                float s = e0 + e1 + e2;
                #pragma unroll
                for (int off = 16; off; off >>= 1)
                    s += __shfl_xor_sync(0xffffffffu, s, off);
                float inv = __fdividef(1.f, s);
                se[lane] = e0 * inv; se[lane + 32] = e1 * inv;
                if (lane == 0) se[64] = e2 * inv;
            }
            __syncthreads();
            float a0 = 0.f, a1 = 0.f;
            #pragma unroll 8
            for (int j = 0; j < TP; j++) {
                float al = se[j];
                const float* hr = g_hs + ((size_t)j * BB + b) * HIDN;
                a0 = fmaf(al, hr[tid], a0);
                a1 = fmaf(al, hr[tid + 256], a1);
            }
            g_ak[((size_t)k * BB + b) * HIDN + tid]       = a0;
            g_ak[((size_t)k * BB + b) * HIDN + tid + 256] = a1;
        }
        gbar(&g_ctr[2], 128u * (++ph));

        // ---- B: cell GEMM + gates (f32x2, pipelined tiles) ----
        ull acc[4];
        #pragma unroll
        for (int g = 0; g < 4; g++)
            acc[g] = dpack(g_xhm[((size_t)k * BB + bB) * G4 + g * 512 + d], 0.f);
        const float* a_in = g_ak + (size_t)k * BB * HIDN;
        const float* h_in = g_hm + (size_t)k * BB * HIDN;
        {
            float4 rr[4];
            ldregs(rr, a_in, bl, ksl);
            for (int ci = 0; ci < 16; ci++) {
                __syncthreads();
                stregs(tile, rr, bl, ksl);
                __syncthreads();
                if (ci + 1 < 16) {
                    const float* srcn = (ci + 1 < 8) ? (a_in + (ci + 1) * 64)
                                                     : (h_in + (ci - 7) * 64);
                    ldregs(rr, srcn, bl, ksl);
                }
                int k0 = ci * 64;
                #pragma unroll
                for (int kk = 0; kk < 64; kk += 4) {
                    float4 hv = *(const float4*)&tile[bB][kk];
                    ull h0 = *(ull*)&hv.x, h1 = *(ull*)&hv.z;
                    #pragma unroll
                    for (int g = 0; g < 4; g++) {
                        float4 wv = *(const float4*)&wcat[(dloc * 4 + g) * 1024 + k0 + kk];
                        ull w0 = *(ull*)&wv.x, w1 = *(ull*)&wv.z;
                        dfma(acc[g], w0, h0);
                        dfma(acc[g], w1, h1);
                    }
                }
            }
        }
        {
            float ig = sigm(dred(acc[0])), fg = sigm(dred(acc[1]));
            float gg = tanhm(dred(acc[2])), og = sigm(dred(acc[3]));
            c_m = fg * c_m + ig * gg;
            g_hm[((size_t)(k + 1) * BB + bB) * HIDN + d] = og * tanhm(c_m);
        }
        gbar(&g_ctr[2], 128u * (++ph));

        // ---- D: wmhm[k+1] = Wm @ h_m (f32x2, pipelined tiles) ----
        {
            const float* hmk = g_hm + (size_t)(k + 1) * BB * HIDN;
            ull s2 = dpack(0.f, 0.f);
            float4 rr[4];
            ldregs(rr, hmk, bl, ksl);
            for (int ci = 0; ci < 8; ci++) {
                __syncthreads();
                stregs(tile, rr, bl, ksl);
                __syncthreads();
                if (ci + 1 < 8) ldregs(rr, hmk + (ci + 1) * 64, bl, ksl);
                int k0 = ci * 64;
                #pragma unroll
                for (int kk = 0; kk < 64; kk += 4) {
                    float4 hv = *(const float4*)&tile[bD][kk];
                    float4 wv = *(const float4*)&wm_s[nl * 512 + k0 + kk];
                    ull h0 = *(ull*)&hv.x, h1 = *(ull*)&hv.z;
                    ull w0 = *(ull*)&wv.x, w1 = *(ull*)&wv.z;
                    dfma(s2, w0, h0);
                    dfma(s2, w1, h1);
                }
            }
            g_wmhm[((size_t)(k + 1) * BB + bD) * HIDN + cta * 4 + nl] = dred(s2);
        }
        if (k < THY - 1) gbar(&g_ctr[2], 128u * (++ph));
    }
}

// ------------------------- final classifier --------------------------------
__global__ void fc_out(const float* __restrict__ fc_w,
                       const float* __restrict__ fc_b,
                       float* __restrict__ out) {
    int b = blockIdx.x;
    int lane = threadIdx.x & 31, c = threadIdx.x >> 5;
    const float* hm = g_hm + (size_t)THY * BB * HIDN + (size_t)b * HIDN;
    const float* wr = fc_w + (size_t)c * HIDN;
    float p = 0.f;
    #pragma unroll 4
    for (int h = lane; h < HIDN; h += 32) p = fmaf(hm[h], wr[h], p);
    #pragma unroll
    for (int off = 16; off; off >>= 1) p += __shfl_xor_sync(0xffffffffu, p, off);
    if (lane == 0) out[b * 3 + c] = p + fc_b[c];
}

// ---------------------------------------------------------------------------
extern "C" void kernel_launch(void* const* d_in, const int* in_sizes, int n_in,
                              void* d_out, int out_size) {
    const float* pair  = (const float*)d_in[0];
    const float* w_e   = (const float*)d_in[3];
    const float* Ws    = (const float*)d_in[4];
    const float* Wt    = (const float*)d_in[5];
    const float* Wm    = (const float*)d_in[6];
    const float* fc_w  = (const float*)d_in[7];
    const float* fc_b  = (const float*)d_in[8];
    const float* Wih_p = (const float*)d_in[9];
    const float* Whh_p = (const float*)d_in[10];
    const float* bih_p = (const float*)d_in[11];
    const float* bhh_p = (const float*)d_in[12];
    const float* Wih_h = (const float*)d_in[13];
    const float* Whh_h = (const float*)d_in[14];
    const float* bih_h = (const float*)d_in[15];
    const float* bhh_h = (const float*)d_in[16];
    const float* Wih_m = (const float*)d_in[17];
    const float* Whh_m = (const float*)d_in[18];
    const float* bih_m = (const float*)d_in[19];
    const float* bhh_m = (const float*)d_in[20];
    float* out = (float*)d_out;

    float *p_xp, *p_xh, *p_xhm, *p_hs, *p_ht, *p_wshs, *p_wtht;
    cudaGetSymbolAddress((void**)&p_xp,   g_xp);
    cudaGetSymbolAddress((void**)&p_xh,   g_xh);
    cudaGetSymbolAddress((void**)&p_xhm,  g_xhm);
    cudaGetSymbolAddress((void**)&p_hs,   g_hs);
    cudaGetSymbolAddress((void**)&p_ht,   g_ht);
    cudaGetSymbolAddress((void**)&p_wshs, g_wshs);
    cudaGetSymbolAddress((void**)&p_wtht, g_wtht);

    __nv_bfloat16 *bxph,*bxpl,*bxhh,*bxhl,*wph,*wpl,*whh,*whl;
    __nv_bfloat16 *wsh,*wsl,*wth,*wtl,*wmrh,*wmrl,*hsh,*hsl,*hth,*htl;
    cudaGetSymbolAddress((void**)&bxph, g_bxph);
    cudaGetSymbolAddress((void**)&bxpl, g_bxpl);
    cudaGetSymbolAddress((void**)&bxhh, g_bxhh);
    cudaGetSymbolAddress((void**)&bxhl, g_bxhl);
    cudaGetSymbolAddress((void**)&wph,  g_wp_h);
    cudaGetSymbolAddress((void**)&wpl,  g_wp_l);
    cudaGetSymbolAddress((void**)&whh,  g_wh_h);
    cudaGetSymbolAddress((void**)&whl,  g_wh_l);
    cudaGetSymbolAddress((void**)&wsh,  g_ws_h);
    cudaGetSymbolAddress((void**)&wsl,  g_ws_l);
    cudaGetSymbolAddress((void**)&wth,  g_wt_h);
    cudaGetSymbolAddress((void**)&wtl,  g_wt_l);
    cudaGetSymbolAddress((void**)&wmrh, g_wmr_h);
    cudaGetSymbolAddress((void**)&wmrl, g_wmr_l);
    cudaGetSymbolAddress((void**)&hsh,  g_hsbh);
    cudaGetSymbolAddress((void**)&hsl,  g_hsbl);
    cudaGetSymbolAddress((void**)&hth,  g_htbh);
    cudaGetSymbolAddress((void**)&htl,  g_htbl);

    static int smem_set = 0;
    int lstm_smem  = (32 * 512 + 64 * 68) * 4;
    int match_smem = (16 * 1024 + 4 * 512 + 64 * 68 + 512 + 512 + 96) * 4;
    if (!smem_set) {
        cudaFuncSetAttribute(lstm_pers,
            cudaFuncAttributeMaxDynamicSharedMemorySize, lstm_smem);
        cudaFuncSetAttribute(match_pers,
            cudaFuncAttributeMaxDynamicSharedMemorySize, match_smem);
        smem_set = 1;
    }

    // Launch order arranged so launch #6 (ncu -s 5 -c 1) is the big GEMM.
    kinit<<<1, 32>>>();                                                   // 1
    conv_pair<<<(MXP * (EMBD/4) + 255)/256, 256>>>(pair, 1, bxph, bxpl, MXP);      // 2
    conv_pair<<<(MXH * (EMBD/4) + 255)/256, 256>>>(pair, 2 + 64, bxhh, bxhl, MXH); // 3
    conv_mat<<<(G4 * (EMBD/4) + 255)/256, 256>>>(Wih_p, EMBD, 0, wph, wpl, G4, EMBD); // 4
    conv_mat<<<(G4 * (EMBD/4) + 255)/256, 256>>>(Wih_h, EMBD, 0, whh, whl, G4, EMBD); // 5
    gemm_bf16<<<dim3(G4/64, (MXP + 127)/128), 256>>>(                      // 6 <- profiled
        bxph, bxpl, wph, wpl, bih_p, bhh_p, p_xp, MXP, G4, EMBD);
    gemm_bf16<<<dim3(G4/64, MXH/128), 256>>>(
        bxhh, bxhl, whh, whl, bih_h, bhh_h, p_xh, MXH, G4, EMBD);

    conv_mat<<<(HIDN * (HIDN/4) + 255)/256, 256>>>(Ws, HIDN, 0, wsh, wsl, HIDN, HIDN);
    conv_mat<<<(HIDN * (HIDN/4) + 255)/256, 256>>>(Wt, HIDN, 0, wth, wtl, HIDN, HIDN);
    conv_mat<<<(G4 * (HIDN/4) + 255)/256, 256>>>(Wih_m, 2 * HIDN, HIDN, wmrh, wmrl, G4, HIDN);

    lstm_pers<<<128, 256, lstm_smem>>>(Whh_p, Whh_h);

    conv_mat<<<(MXP * (HIDN/4) + 255)/256, 256>>>(p_hs, HIDN, 0, hsh, hsl, MXP, HIDN);
    conv_mat<<<(MXH * (HIDN/4) + 255)/256, 256>>>(p_ht, HIDN, 0, hth, htl, MXH, HIDN);
    gemm_bf16<<<dim3(HIDN/64, (MXP + 127)/128), 256>>>(
        hsh, hsl, wsh, wsl, nullptr, nullptr, p_wshs, MXP, HIDN, HIDN);
    gemm_bf16<<<dim3(HIDN/64, MXH/128), 256>>>(
        hth, htl, wth, wtl, nullptr, nullptr, p_wtht, MXH, HIDN, HIDN);
    gemm_bf16<<<dim3(G4/64, MXH/128), 256>>>(
        hth, htl, wmrh, wmrl, bih_m, bhh_m, p_xhm, MXH, G4, HIDN);

    match_pers<<<128, 256, match_smem>>>(Wih_m, Whh_m, Wm, w_e);

    fc_out<<<64, 96>>>(fc_w, fc_b, out);
}